// round 5
// baseline (speedup 1.0000x reference)
#include <cuda_runtime.h>
#include <cuda_bf16.h>
#include <math.h>
#include <stdint.h>

// ---------------------------------------------------------------------------
// Problem dims (fixed)
// ---------------------------------------------------------------------------
#define BATCH   32
#define SEQ     512
#define DMODEL  512
#define NHEADS  8
#define HDIM    64
#define DFF     2048
#define MTOK    (BATCH * SEQ)
#define LN_EPS  1e-12f

// ---------------------------------------------------------------------------
// Scratch (device globals)
// ---------------------------------------------------------------------------
__device__ float g_t0[MTOK * DMODEL];
__device__ float g_attnln[MTOK * DMODEL];

__device__ __nv_bfloat16 g_xhi[MTOK * DMODEL];
__device__ __nv_bfloat16 g_xlo[MTOK * DMODEL];
__device__ __nv_bfloat16 g_qhi[MTOK * DMODEL];
__device__ __nv_bfloat16 g_qlo[MTOK * DMODEL];
__device__ __nv_bfloat16 g_khi[MTOK * DMODEL];
__device__ __nv_bfloat16 g_klo[MTOK * DMODEL];
__device__ __nv_bfloat16 g_vhi[MTOK * DMODEL];
__device__ __nv_bfloat16 g_vlo[MTOK * DMODEL];
__device__ __nv_bfloat16 g_chi[MTOK * DMODEL];
__device__ __nv_bfloat16 g_clo[MTOK * DMODEL];
__device__ __nv_bfloat16 g_ahi[MTOK * DMODEL];
__device__ __nv_bfloat16 g_alo[MTOK * DMODEL];
__device__ __nv_bfloat16 g_fhi[MTOK * DFF];
__device__ __nv_bfloat16 g_flo[MTOK * DFF];

__device__ __nv_bfloat16 g_wqhi[DMODEL * DMODEL];
__device__ __nv_bfloat16 g_wqlo[DMODEL * DMODEL];
__device__ __nv_bfloat16 g_wkhi[DMODEL * DMODEL];
__device__ __nv_bfloat16 g_wklo[DMODEL * DMODEL];
__device__ __nv_bfloat16 g_wvhi[DMODEL * DMODEL];
__device__ __nv_bfloat16 g_wvlo[DMODEL * DMODEL];
__device__ __nv_bfloat16 g_wohi[DMODEL * DMODEL];
__device__ __nv_bfloat16 g_wolo[DMODEL * DMODEL];
__device__ __nv_bfloat16 g_w1hi[DFF * DMODEL];
__device__ __nv_bfloat16 g_w1lo[DFF * DMODEL];
__device__ __nv_bfloat16 g_w2hi[DMODEL * DFF];
__device__ __nv_bfloat16 g_w2lo[DMODEL * DFF];

// ---------------------------------------------------------------------------
// helpers
// ---------------------------------------------------------------------------
__device__ __forceinline__ void mma16816(float* c, const uint32_t* a, const uint32_t* b)
{
    asm volatile(
        "mma.sync.aligned.m16n8k16.row.col.f32.bf16.bf16.f32 "
        "{%0,%1,%2,%3}, {%4,%5,%6,%7}, {%8,%9}, {%0,%1,%2,%3};"
        : "+f"(c[0]), "+f"(c[1]), "+f"(c[2]), "+f"(c[3])
        : "r"(a[0]), "r"(a[1]), "r"(a[2]), "r"(a[3]), "r"(b[0]), "r"(b[1]));
}

__device__ __forceinline__ uint32_t smem_u32(const void* p) {
    uint32_t a;
    asm("{ .reg .u64 t; cvta.to.shared.u64 t, %1; cvt.u32.u64 %0, t; }"
        : "=r"(a) : "l"(p));
    return a;
}

__device__ __forceinline__ void cp16(uint32_t dst, const void* src) {
    asm volatile("cp.async.cg.shared.global [%0], [%1], 16;"
                 :: "r"(dst), "l"(src));
}
__device__ __forceinline__ void cp_commit() {
    asm volatile("cp.async.commit_group;" ::: "memory");
}
template <int N>
__device__ __forceinline__ void cp_wait() {
    asm volatile("cp.async.wait_group %0;" :: "n"(N) : "memory");
}

__device__ __forceinline__ float fast_exp(float x) {
    float y = fmaxf(x * 1.4426950408889634f, -120.0f);
    float n = rintf(y);
    float f = y - n;
    float p = 1.3333558e-3f;
    p = fmaf(p, f, 9.6181291e-3f);
    p = fmaf(p, f, 5.5504109e-2f);
    p = fmaf(p, f, 2.4022651e-1f);
    p = fmaf(p, f, 6.9314718e-1f);
    p = fmaf(p, f, 1.0f);
    return p * __int_as_float(((int)n + 127) << 23);
}

__device__ __forceinline__ void split1(float v, unsigned short& h, unsigned short& l) {
    __nv_bfloat16 hb = __float2bfloat16_rn(v);
    float r = v - __bfloat162float(hb);
    __nv_bfloat16 lb = __float2bfloat16_rn(r);
    h = __bfloat16_as_ushort(hb);
    l = __bfloat16_as_ushort(lb);
}
__device__ __forceinline__ uint32_t pack2(unsigned short a, unsigned short b) {
    return (uint32_t)a | ((uint32_t)b << 16);
}

// ---------------------------------------------------------------------------
// fp32 -> bf16 hi/lo split (input x only)
// ---------------------------------------------------------------------------
__global__ void split_kernel(const float* __restrict__ X,
                             __nv_bfloat16* __restrict__ hi,
                             __nv_bfloat16* __restrict__ lo, int n4)
{
    int i = blockIdx.x * blockDim.x + threadIdx.x;
    if (i >= n4) return;
    float4 x = ((const float4*)X)[i];
    unsigned short h0, h1, h2, h3, l0, l1, l2, l3;
    split1(x.x, h0, l0); split1(x.y, h1, l1);
    split1(x.z, h2, l2); split1(x.w, h3, l3);
    uint2 hv, lv;
    hv.x = pack2(h0, h1); hv.y = pack2(h2, h3);
    lv.x = pack2(l0, l1); lv.y = pack2(l2, l3);
    ((uint2*)hi)[i] = hv;
    ((uint2*)lo)[i] = lv;
}

// Transpose + split: W[K][N] fp32 -> hi/lo [N][K] bf16
__global__ void tsplit_kernel(const float* __restrict__ W,
                              __nv_bfloat16* __restrict__ hi,
                              __nv_bfloat16* __restrict__ lo,
                              int K, int N)
{
    __shared__ float tile[32][33];
    const int n0 = blockIdx.x * 32, k0 = blockIdx.y * 32;
    const int tx = threadIdx.x, ty = threadIdx.y;
#pragma unroll
    for (int i = 0; i < 32; i += 8)
        tile[ty + i][tx] = W[(size_t)(k0 + ty + i) * N + n0 + tx];
    __syncthreads();
#pragma unroll
    for (int i = 0; i < 32; i += 8) {
        float v = tile[tx][ty + i];
        unsigned short h, l;
        split1(v, h, l);
        size_t o = (size_t)(n0 + ty + i) * K + k0 + tx;
        hi[o] = __ushort_as_bfloat16(h);
        lo[o] = __ushort_as_bfloat16(l);
    }
}

// ---------------------------------------------------------------------------
// Double-buffered tensor-core split-GEMM.
//   C = (Ahi+Alo)[M,K] @ (Bhi+Blo)[N,K]^T + bias
//   outputs: Cf (fp32, nullable), Chi/Clo (bf16 split, nullable)
//   do_gelu applied before outputs.
// CTA 128x64, k-tile 64, 2-stage cp.async pipeline.
// ---------------------------------------------------------------------------
#define SA 72
#define ST_A (128 * SA)                 // per array elems
#define ST_B (64 * SA)
#define STAGE_ELEMS (2 * ST_A + 2 * ST_B)   // 27648
#define GM_SMEM_BYTES (2 * STAGE_ELEMS * 2) // 110592

__global__ __launch_bounds__(256)
void gemm_mma(const __nv_bfloat16* __restrict__ Ahi,
              const __nv_bfloat16* __restrict__ Alo,
              const __nv_bfloat16* __restrict__ Bhi,
              const __nv_bfloat16* __restrict__ Blo,
              const float* __restrict__ bias,
              float* __restrict__ Cf,
              __nv_bfloat16* __restrict__ Chi,
              __nv_bfloat16* __restrict__ Clo,
              int M, int N, int K, int do_gelu)
{
    extern __shared__ __nv_bfloat16 smb[];
    const uint32_t sm_base = smem_u32(smb);

    const int tid = threadIdx.x;
    const int wid = tid >> 5;
    const int lid = tid & 31;
    const int gID = lid >> 2;
    const int t4  = lid & 3;

    const int row0 = blockIdx.y * 128;
    const int col0 = blockIdx.x * 64;
    const int m_off = (wid & 3) * 32;
    const int n_off = (wid >> 2) * 32;

    // per-thread load coords
    const int ar = tid >> 1;             // A: 128 rows, 2 threads/row (g=0..7 via i)
    const int ag = (tid & 1) * 4;        //    each thread 4 uint4 chunks
    const int br = tid >> 2;             // B: 64 rows, 4 threads/row
    const int bg = (tid & 3) * 2;        //    each thread 2 uint4 chunks

    const int nT = K >> 6;

    // ---- stage loader ----
    auto load_stage = [&](int buf, int t) {
        const int kb = t << 6;
        uint32_t base = sm_base + (uint32_t)buf * STAGE_ELEMS * 2;
        uint32_t a_hi = base;
        uint32_t a_lo = base + ST_A * 2;
        uint32_t b_hi = base + 2 * ST_A * 2;
        uint32_t b_lo = base + 2 * ST_A * 2 + ST_B * 2;
#pragma unroll
        for (int i = 0; i < 4; i++) {
            int g = ag + i;
            uint32_t ds = (uint32_t)(ar * SA + g * 8) * 2;
            size_t src = (size_t)(row0 + ar) * K + kb + g * 8;
            cp16(a_hi + ds, Ahi + src);
            cp16(a_lo + ds, Alo + src);
        }
#pragma unroll
        for (int i = 0; i < 2; i++) {
            int g = bg + i;
            uint32_t ds = (uint32_t)(br * SA + g * 8) * 2;
            size_t src = (size_t)(col0 + br) * K + kb + g * 8;
            cp16(b_hi + ds, Bhi + src);
            cp16(b_lo + ds, Blo + src);
        }
        cp_commit();
    };

    float acc[2][4][4];
#pragma unroll
    for (int mi = 0; mi < 2; mi++)
#pragma unroll
        for (int ni = 0; ni < 4; ni++)
#pragma unroll
            for (int j = 0; j < 4; j++) acc[mi][ni][j] = 0.f;

    load_stage(0, 0);

    for (int t = 0; t < nT; t++) {
        const int buf = t & 1;
        if (t + 1 < nT) {
            load_stage(1 - buf, t + 1);
            cp_wait<1>();
        } else {
            cp_wait<0>();
        }
        __syncthreads();

        const __nv_bfloat16* As_hi = smb + buf * STAGE_ELEMS;
        const __nv_bfloat16* As_lo = As_hi + ST_A;
        const __nv_bfloat16* Bs_hi = As_hi + 2 * ST_A;
        const __nv_bfloat16* Bs_lo = Bs_hi + ST_B;

#pragma unroll
        for (int kk = 0; kk < 64; kk += 16) {
            uint32_t ahi[2][4], alo[2][4], bhi[4][2], blo[4][2];
#pragma unroll
            for (int mi = 0; mi < 2; mi++) {
                int r = m_off + mi * 16 + gID;
                int base0 = r * SA + kk + t4 * 2;
                int base1 = (r + 8) * SA + kk + t4 * 2;
                ahi[mi][0] = *(const uint32_t*)&As_hi[base0];
                ahi[mi][1] = *(const uint32_t*)&As_hi[base1];
                ahi[mi][2] = *(const uint32_t*)&As_hi[base0 + 8];
                ahi[mi][3] = *(const uint32_t*)&As_hi[base1 + 8];
                alo[mi][0] = *(const uint32_t*)&As_lo[base0];
                alo[mi][1] = *(const uint32_t*)&As_lo[base1];
                alo[mi][2] = *(const uint32_t*)&As_lo[base0 + 8];
                alo[mi][3] = *(const uint32_t*)&As_lo[base1 + 8];
            }
#pragma unroll
            for (int ni = 0; ni < 4; ni++) {
                int n = n_off + ni * 8 + gID;
                int base = n * SA + kk + t4 * 2;
                bhi[ni][0] = *(const uint32_t*)&Bs_hi[base];
                bhi[ni][1] = *(const uint32_t*)&Bs_hi[base + 8];
                blo[ni][0] = *(const uint32_t*)&Bs_lo[base];
                blo[ni][1] = *(const uint32_t*)&Bs_lo[base + 8];
            }
#pragma unroll
            for (int mi = 0; mi < 2; mi++)
#pragma unroll
                for (int ni = 0; ni < 4; ni++) {
                    mma16816(acc[mi][ni], ahi[mi], bhi[ni]);
                    mma16816(acc[mi][ni], alo[mi], bhi[ni]);
                    mma16816(acc[mi][ni], ahi[mi], blo[ni]);
                }
        }
        __syncthreads();
    }

    // ---- epilogue ----
#pragma unroll
    for (int mi = 0; mi < 2; mi++) {
#pragma unroll
        for (int ni = 0; ni < 4; ni++) {
            int col = col0 + n_off + ni * 8 + t4 * 2;
            float b0 = bias[col], b1 = bias[col + 1];
#pragma unroll
            for (int half = 0; half < 2; half++) {
                int row = row0 + m_off + mi * 16 + gID + half * 8;
                float v0 = acc[mi][ni][half * 2 + 0] + b0;
                float v1 = acc[mi][ni][half * 2 + 1] + b1;
                if (do_gelu) {
                    v0 = 0.5f * v0 * (1.0f + erff(v0 * 0.70710678118654752f));
                    v1 = 0.5f * v1 * (1.0f + erff(v1 * 0.70710678118654752f));
                }
                size_t o = (size_t)row * N + col;
                if (Cf) {
                    float2 fo; fo.x = v0; fo.y = v1;
                    *(float2*)(Cf + o) = fo;
                }
                if (Chi) {
                    unsigned short h0, h1, l0, l1;
                    split1(v0, h0, l0);
                    split1(v1, h1, l1);
                    *(uint32_t*)(Chi + o) = pack2(h0, h1);
                    *(uint32_t*)(Clo + o) = pack2(l0, l1);
                }
            }
        }
    }
}

// ---------------------------------------------------------------------------
// Tensor-core attention. Q/K/V arrive pre-split bf16. ctx written pre-split.
// ---------------------------------------------------------------------------
#define AT_SA   72
#define AT_QHI  0
#define AT_QLO  9216
#define AT_KHI  18432
#define AT_KLO  27648
#define AT_PHI  36864
#define AT_PLO  46080
#define AT_SS   55296
#define AT_INV  (AT_SS + 64 * 512 * 4)
#define AT_SMEM (AT_INV + 256)

__global__ __launch_bounds__(256)
void attn_mma(const __nv_bfloat16* __restrict__ Qhi_g,
              const __nv_bfloat16* __restrict__ Qlo_g,
              const __nv_bfloat16* __restrict__ Khi_g,
              const __nv_bfloat16* __restrict__ Klo_g,
              const __nv_bfloat16* __restrict__ Vhi_g,
              const __nv_bfloat16* __restrict__ Vlo_g,
              const float* __restrict__ mask,
              __nv_bfloat16* __restrict__ Chi_g,
              __nv_bfloat16* __restrict__ Clo_g)
{
    extern __shared__ char smc[];
    __nv_bfloat16* Qhi = (__nv_bfloat16*)(smc + AT_QHI);
    __nv_bfloat16* Qlo = (__nv_bfloat16*)(smc + AT_QLO);
    __nv_bfloat16* Khi = (__nv_bfloat16*)(smc + AT_KHI);
    __nv_bfloat16* Klo = (__nv_bfloat16*)(smc + AT_KLO);
    __nv_bfloat16* Phi = (__nv_bfloat16*)(smc + AT_PHI);
    __nv_bfloat16* Plo = (__nv_bfloat16*)(smc + AT_PLO);
    float* Ss   = (float*)(smc + AT_SS);
    float* invs = (float*)(smc + AT_INV);

    const int tid = threadIdx.x;
    const int wid = tid >> 5, lid = tid & 31;
    const int gID = lid >> 2, t4 = lid & 3;
    const int wm = wid & 3, wn = wid >> 2;
    const int q0 = blockIdx.x * 64;
    const int h = blockIdx.y, b = blockIdx.z;
    const size_t hb = ((size_t)b * SEQ) * DMODEL + (size_t)h * HDIM;
    const float* mbase = mask + (size_t)b * SEQ * SEQ;

    // load Q tile 64x64 (bf16 hi/lo, direct copy)
#pragma unroll
    for (int i = 0; i < 2; i++) {
        int e = tid + i * 256;
        int r = e >> 3, g = e & 7;
        size_t src = hb + (size_t)(q0 + r) * DMODEL + g * 8;
        int ds = r * AT_SA + g * 8;
        *(uint4*)(Qhi + ds) = *(const uint4*)(Qhi_g + src);
        *(uint4*)(Qlo + ds) = *(const uint4*)(Qlo_g + src);
    }

    float pv[4][4];
#pragma unroll
    for (int ni = 0; ni < 4; ni++)
#pragma unroll
        for (int j = 0; j < 4; j++) pv[ni][j] = 0.f;

    // ---- phase 1: scores ----
    for (int kc = 0; kc < 8; kc++) {
        const int k0 = kc * 64;
        __syncthreads();
#pragma unroll
        for (int i = 0; i < 2; i++) {
            int e = tid + i * 256;
            int r = e >> 3, g = e & 7;
            size_t src = hb + (size_t)(k0 + r) * DMODEL + g * 8;
            int ds = r * AT_SA + g * 8;
            *(uint4*)(Khi + ds) = *(const uint4*)(Khi_g + src);
            *(uint4*)(Klo + ds) = *(const uint4*)(Klo_g + src);
        }
        __syncthreads();

        float s[4][4];
#pragma unroll
        for (int ni = 0; ni < 4; ni++)
#pragma unroll
            for (int j = 0; j < 4; j++) s[ni][j] = 0.f;

#pragma unroll
        for (int kk = 0; kk < 64; kk += 16) {
            uint32_t ah[4], al[4];
            int rb0 = (wm * 16 + gID) * AT_SA + kk + t4 * 2;
            int rb1 = rb0 + 8 * AT_SA;
            ah[0] = *(const uint32_t*)&Qhi[rb0];
            ah[1] = *(const uint32_t*)&Qhi[rb1];
            ah[2] = *(const uint32_t*)&Qhi[rb0 + 8];
            ah[3] = *(const uint32_t*)&Qhi[rb1 + 8];
            al[0] = *(const uint32_t*)&Qlo[rb0];
            al[1] = *(const uint32_t*)&Qlo[rb1];
            al[2] = *(const uint32_t*)&Qlo[rb0 + 8];
            al[3] = *(const uint32_t*)&Qlo[rb1 + 8];
#pragma unroll
            for (int ni = 0; ni < 4; ni++) {
                int nb = (wn * 32 + ni * 8 + gID) * AT_SA + kk + t4 * 2;
                uint32_t bh[2], bl[2];
                bh[0] = *(const uint32_t*)&Khi[nb];
                bh[1] = *(const uint32_t*)&Khi[nb + 8];
                bl[0] = *(const uint32_t*)&Klo[nb];
                bl[1] = *(const uint32_t*)&Klo[nb + 8];
                mma16816(s[ni], ah, bh);
                mma16816(s[ni], al, bh);
                mma16816(s[ni], ah, bl);
            }
        }
#pragma unroll
        for (int ni = 0; ni < 4; ni++) {
            int col = k0 + wn * 32 + ni * 8 + t4 * 2;
#pragma unroll
            for (int hf = 0; hf < 2; hf++) {
                int row = wm * 16 + gID + hf * 8;
                float2 m2 = *(const float2*)(mbase + (size_t)(q0 + row) * SEQ + col);
                float2 o;
                o.x = s[ni][hf * 2 + 0] * 0.125f + m2.x;
                o.y = s[ni][hf * 2 + 1] * 0.125f + m2.y;
                *(float2*)(Ss + row * 512 + col) = o;
            }
        }
    }
    __syncthreads();

    // ---- phase 2: softmax ----
    {
#pragma unroll
        for (int rr = 0; rr < 8; rr++) {
            int r = wid * 8 + rr;
            float* row = Ss + r * 512;
            float4 v[4];
#pragma unroll
            for (int it = 0; it < 4; it++)
                v[it] = *(float4*)(row + it * 128 + lid * 4);
            float m = -1e30f;
#pragma unroll
            for (int it = 0; it < 4; it++)
                m = fmaxf(m, fmaxf(fmaxf(v[it].x, v[it].y), fmaxf(v[it].z, v[it].w)));
#pragma unroll
            for (int off = 16; off; off >>= 1)
                m = fmaxf(m, __shfl_xor_sync(0xffffffffu, m, off));
            float sum = 0.f;
#pragma unroll
            for (int it = 0; it < 4; it++) {
                v[it].x = fast_exp(v[it].x - m);
                v[it].y = fast_exp(v[it].y - m);
                v[it].z = fast_exp(v[it].z - m);
                v[it].w = fast_exp(v[it].w - m);
                sum += v[it].x + v[it].y + v[it].z + v[it].w;
                *(float4*)(row + it * 128 + lid * 4) = v[it];
            }
#pragma unroll
            for (int off = 16; off; off >>= 1)
                sum += __shfl_xor_sync(0xffffffffu, sum, off);
            if (lid == 0) invs[r] = 1.0f / sum;
        }
    }

    // ---- phase 3: P @ V ----
    for (int kc = 0; kc < 8; kc++) {
        const int k0 = kc * 64;
        __syncthreads();

        // P chunk: normalize + split
        {
            int r = tid >> 2, c0 = (tid & 3) * 16;
            float is = invs[r];
#pragma unroll
            for (int j2 = 0; j2 < 2; j2++) {
                const float* src = Ss + r * 512 + k0 + c0 + j2 * 8;
                float4 a = *(const float4*)(src);
                float4 bq = *(const float4*)(src + 4);
                float vals[8] = {a.x * is, a.y * is, a.z * is, a.w * is,
                                 bq.x * is, bq.y * is, bq.z * is, bq.w * is};
                unsigned short hh[8], ll[8];
#pragma unroll
                for (int j = 0; j < 8; j++) split1(vals[j], hh[j], ll[j]);
                uint4 hv, lv;
                hv.x = pack2(hh[0], hh[1]); hv.y = pack2(hh[2], hh[3]);
                hv.z = pack2(hh[4], hh[5]); hv.w = pack2(hh[6], hh[7]);
                lv.x = pack2(ll[0], ll[1]); lv.y = pack2(ll[2], ll[3]);
                lv.z = pack2(ll[4], ll[5]); lv.w = pack2(ll[6], ll[7]);
                *(uint4*)(Phi + r * AT_SA + c0 + j2 * 8) = hv;
                *(uint4*)(Plo + r * AT_SA + c0 + j2 * 8) = lv;
            }
        }

        // V chunk: transpose (bf16, no split needed)
#pragma unroll
        for (int i = 0; i < 4; i++) {
            int e = tid + i * 256;
            int r = e >> 4, c4 = e & 15;           // uint2 = 4 bf16
            size_t src = hb + (size_t)(k0 + r) * DMODEL + c4 * 4;
            uint2 hv = *(const uint2*)(Vhi_g + src);
            uint2 lv = *(const uint2*)(Vlo_g + src);
            __nv_bfloat16 h0 = __ushort_as_bfloat16((unsigned short)(hv.x & 0xffff));
            __nv_bfloat16 h1 = __ushort_as_bfloat16((unsigned short)(hv.x >> 16));
            __nv_bfloat16 h2 = __ushort_as_bfloat16((unsigned short)(hv.y & 0xffff));
            __nv_bfloat16 h3 = __ushort_as_bfloat16((unsigned short)(hv.y >> 16));
            __nv_bfloat16 l0 = __ushort_as_bfloat16((unsigned short)(lv.x & 0xffff));
            __nv_bfloat16 l1 = __ushort_as_bfloat16((unsigned short)(lv.x >> 16));
            __nv_bfloat16 l2 = __ushort_as_bfloat16((unsigned short)(lv.y & 0xffff));
            __nv_bfloat16 l3 = __ushort_as_bfloat16((unsigned short)(lv.y >> 16));
            int d = c4 * 4;
            Khi[(d + 0) * AT_SA + r] = h0;  Klo[(d + 0) * AT_SA + r] = l0;
            Khi[(d + 1) * AT_SA + r] = h1;  Klo[(d + 1) * AT_SA + r] = l1;
            Khi[(d + 2) * AT_SA + r] = h2;  Klo[(d + 2) * AT_SA + r] = l2;
            Khi[(d + 3) * AT_SA + r] = h3;  Klo[(d + 3) * AT_SA + r] = l3;
        }
        __syncthreads();

#pragma unroll
        for (int kk = 0; kk < 64; kk += 16) {
            uint32_t ah[4], al[4];
            int rb0 = (wm * 16 + gID) * AT_SA + kk + t4 * 2;
            int rb1 = rb0 + 8 * AT_SA;
            ah[0] = *(const uint32_t*)&Phi[rb0];
            ah[1] = *(const uint32_t*)&Phi[rb1];
            ah[2] = *(const uint32_t*)&Phi[rb0 + 8];
            ah[3] = *(const uint32_t*)&Phi[rb1 + 8];
            al[0] = *(const uint32_t*)&Plo[rb0];
            al[1] = *(const uint32_t*)&Plo[rb1];
            al[2] = *(const uint32_t*)&Plo[rb0 + 8];
            al[3] = *(const uint32_t*)&Plo[rb1 + 8];
#pragma unroll
            for (int ni = 0; ni < 4; ni++) {
                int nb = (wn * 32 + ni * 8 + gID) * AT_SA + kk + t4 * 2;
                uint32_t bh[2], bl[2];
                bh[0] = *(const uint32_t*)&Khi[nb];
                bh[1] = *(const uint32_t*)&Khi[nb + 8];
                bl[0] = *(const uint32_t*)&Klo[nb];
                bl[1] = *(const uint32_t*)&Klo[nb + 8];
                mma16816(pv[ni], ah, bh);
                mma16816(pv[ni], al, bh);
                mma16816(pv[ni], ah, bl);
            }
        }
    }

    // ---- write ctx as bf16 hi/lo ----
#pragma unroll
    for (int ni = 0; ni < 4; ni++) {
        int d = wn * 32 + ni * 8 + t4 * 2;
#pragma unroll
        for (int hf = 0; hf < 2; hf++) {
            int row = wm * 16 + gID + hf * 8;
            unsigned short h0, h1, l0, l1;
            split1(pv[ni][hf * 2 + 0], h0, l0);
            split1(pv[ni][hf * 2 + 1], h1, l1);
            size_t o = hb + (size_t)(q0 + row) * DMODEL + d;
            *(uint32_t*)(Chi_g + o) = pack2(h0, h1);
            *(uint32_t*)(Clo_g + o) = pack2(l0, l1);
        }
    }
}

// ---------------------------------------------------------------------------
// LayerNorm + residual; optional bf16 hi/lo side outputs
// ---------------------------------------------------------------------------
__global__ void ln_residual_kernel(const float* __restrict__ y,
                                   const float* __restrict__ res,
                                   const float* __restrict__ g,
                                   const float* __restrict__ bta,
                                   float* __restrict__ out,
                                   __nv_bfloat16* __restrict__ ohi,
                                   __nv_bfloat16* __restrict__ olo)
{
    __shared__ float red[256];
    const int r = blockIdx.x;
    const int tid = threadIdx.x;
    const size_t off = (size_t)r * DMODEL;

    float v0 = y[off + tid]        + res[off + tid];
    float v1 = y[off + tid + 256]  + res[off + tid + 256];

    red[tid] = v0 + v1;
    __syncthreads();
#pragma unroll
    for (int s = 128; s; s >>= 1) {
        if (tid < s) red[tid] += red[tid + s];
        __syncthreads();
    }
    float mean = red[0] * (1.0f / 512.0f);
    __syncthreads();

    float d0 = v0 - mean, d1 = v1 - mean;
    red[tid] = d0 * d0 + d1 * d1;
    __syncthreads();
#pragma unroll
    for (int s = 128; s; s >>= 1) {
        if (tid < s) red[tid] += red[tid + s];
        __syncthreads();
    }
    float inv = rsqrtf(red[0] * (1.0f / 512.0f) + LN_EPS);

    float o0 = d0 * inv * g[tid]       + bta[tid];
    float o1 = d1 * inv * g[tid + 256] + bta[tid + 256];
    out[off + tid]       = o0;
    out[off + tid + 256] = o1;
    if (ohi) {
        unsigned short h, l;
        split1(o0, h, l);
        ohi[off + tid] = __ushort_as_bfloat16(h);
        olo[off + tid] = __ushort_as_bfloat16(l);
        split1(o1, h, l);
        ohi[off + tid + 256] = __ushort_as_bfloat16(h);
        olo[off + tid + 256] = __ushort_as_bfloat16(l);
    }
}

// ---------------------------------------------------------------------------
// launch
// ---------------------------------------------------------------------------
extern "C" void kernel_launch(void* const* d_in, const int* in_sizes, int n_in,
                              void* d_out, int out_size)
{
    const float* x     = (const float*)d_in[0];
    const float* mask  = (const float*)d_in[1];
    const float* Wq    = (const float*)d_in[2];
    const float* bq    = (const float*)d_in[3];
    const float* Wk    = (const float*)d_in[4];
    const float* bk    = (const float*)d_in[5];
    const float* Wv    = (const float*)d_in[6];
    const float* bv    = (const float*)d_in[7];
    const float* Wo    = (const float*)d_in[8];
    const float* bo    = (const float*)d_in[9];
    const float* ln1g  = (const float*)d_in[10];
    const float* ln1b  = (const float*)d_in[11];
    const float* W1    = (const float*)d_in[12];
    const float* b1    = (const float*)d_in[13];
    const float* W2    = (const float*)d_in[14];
    const float* b2    = (const float*)d_in[15];
    const float* ln2g  = (const float*)d_in[16];
    const float* ln2b  = (const float*)d_in[17];
    float* out = (float*)d_out;

    float *t0, *aln;
    cudaGetSymbolAddress((void**)&t0,  g_t0);
    cudaGetSymbolAddress((void**)&aln, g_attnln);

    __nv_bfloat16 *xhi, *xlo, *qhi, *qlo, *khi, *klo, *vhi, *vlo;
    __nv_bfloat16 *chi, *clo, *ahi, *alo, *fhi, *flo;
    cudaGetSymbolAddress((void**)&xhi, g_xhi);
    cudaGetSymbolAddress((void**)&xlo, g_xlo);
    cudaGetSymbolAddress((void**)&qhi, g_qhi);
    cudaGetSymbolAddress((void**)&qlo, g_qlo);
    cudaGetSymbolAddress((void**)&khi, g_khi);
    cudaGetSymbolAddress((void**)&klo, g_klo);
    cudaGetSymbolAddress((void**)&vhi, g_vhi);
    cudaGetSymbolAddress((void**)&vlo, g_vlo);
    cudaGetSymbolAddress((void**)&chi, g_chi);
    cudaGetSymbolAddress((void**)&clo, g_clo);
    cudaGetSymbolAddress((void**)&ahi, g_ahi);
    cudaGetSymbolAddress((void**)&alo, g_alo);
    cudaGetSymbolAddress((void**)&fhi, g_fhi);
    cudaGetSymbolAddress((void**)&flo, g_flo);

    __nv_bfloat16 *wqh, *wql, *wkh, *wkl, *wvh, *wvl, *woh, *wol, *w1h, *w1l, *w2h, *w2l;
    cudaGetSymbolAddress((void**)&wqh, g_wqhi);
    cudaGetSymbolAddress((void**)&wql, g_wqlo);
    cudaGetSymbolAddress((void**)&wkh, g_wkhi);
    cudaGetSymbolAddress((void**)&wkl, g_wklo);
    cudaGetSymbolAddress((void**)&wvh, g_wvhi);
    cudaGetSymbolAddress((void**)&wvl, g_wvlo);
    cudaGetSymbolAddress((void**)&woh, g_wohi);
    cudaGetSymbolAddress((void**)&wol, g_wolo);
    cudaGetSymbolAddress((void**)&w1h, g_w1hi);
    cudaGetSymbolAddress((void**)&w1l, g_w1lo);
    cudaGetSymbolAddress((void**)&w2h, g_w2hi);
    cudaGetSymbolAddress((void**)&w2l, g_w2lo);

    cudaFuncSetAttribute(attn_mma,
                         cudaFuncAttributeMaxDynamicSharedMemorySize, AT_SMEM);
    cudaFuncSetAttribute(gemm_mma,
                         cudaFuncAttributeMaxDynamicSharedMemorySize, GM_SMEM_BYTES);

    dim3 tb(32, 8);

    // weight transpose + split
    tsplit_kernel<<<dim3(DMODEL / 32, DMODEL / 32), tb>>>(Wq, wqh, wql, DMODEL, DMODEL);
    tsplit_kernel<<<dim3(DMODEL / 32, DMODEL / 32), tb>>>(Wk, wkh, wkl, DMODEL, DMODEL);
    tsplit_kernel<<<dim3(DMODEL / 32, DMODEL / 32), tb>>>(Wv, wvh, wvl, DMODEL, DMODEL);
    tsplit_kernel<<<dim3(DMODEL / 32, DMODEL / 32), tb>>>(Wo, woh, wol, DMODEL, DMODEL);
    tsplit_kernel<<<dim3(DFF / 32, DMODEL / 32), tb>>>(W1, w1h, w1l, DMODEL, DFF);
    tsplit_kernel<<<dim3(DMODEL / 32, DFF / 32), tb>>>(W2, w2h, w2l, DFF, DMODEL);

    // split input x
    {
        int n4 = MTOK * DMODEL / 4;
        split_kernel<<<(n4 + 255) / 256, 256>>>(x, xhi, xlo, n4);
    }

    // QKV projections -> bf16 hi/lo directly
    {
        dim3 grid(DMODEL / 64, MTOK / 128);
        gemm_mma<<<grid, 256, GM_SMEM_BYTES>>>(xhi, xlo, wqh, wql, bq,
                                               nullptr, qhi, qlo,
                                               MTOK, DMODEL, DMODEL, 0);
        gemm_mma<<<grid, 256, GM_SMEM_BYTES>>>(xhi, xlo, wkh, wkl, bk,
                                               nullptr, khi, klo,
                                               MTOK, DMODEL, DMODEL, 0);
        gemm_mma<<<grid, 256, GM_SMEM_BYTES>>>(xhi, xlo, wvh, wvl, bv,
                                               nullptr, vhi, vlo,
                                               MTOK, DMODEL, DMODEL, 0);
    }

    // attention -> ctx bf16 hi/lo directly
    {
        dim3 grid(SEQ / 64, NHEADS, BATCH);
        attn_mma<<<grid, 256, AT_SMEM>>>(qhi, qlo, khi, klo, vhi, vlo,
                                         mask, chi, clo);
    }

    // output projection + residual LN (LN emits fp32 + bf16 hi/lo)
    {
        dim3 grid(DMODEL / 64, MTOK / 128);
        gemm_mma<<<grid, 256, GM_SMEM_BYTES>>>(chi, clo, woh, wol, bo,
                                               t0, nullptr, nullptr,
                                               MTOK, DMODEL, DMODEL, 0);
        ln_residual_kernel<<<MTOK, 256>>>(t0, x, ln1g, ln1b, aln, ahi, alo);
    }

    // FFN
    {
        dim3 grid1(DFF / 64, MTOK / 128);
        gemm_mma<<<grid1, 256, GM_SMEM_BYTES>>>(ahi, alo, w1h, w1l, b1,
                                                nullptr, fhi, flo,
                                                MTOK, DFF, DMODEL, 1);
        dim3 grid2(DMODEL / 64, MTOK / 128);
        gemm_mma<<<grid2, 256, GM_SMEM_BYTES>>>(fhi, flo, w2h, w2l, b2,
                                                t0, nullptr, nullptr,
                                                MTOK, DMODEL, DFF, 0);
        ln_residual_kernel<<<MTOK, 256>>>(t0, aln, ln2g, ln2b, out,
                                          nullptr, nullptr);
    }
}

// round 6
// speedup vs baseline: 1.1135x; 1.1135x over previous
#include <cuda_runtime.h>
#include <cuda_bf16.h>
#include <math.h>
#include <stdint.h>

// ---------------------------------------------------------------------------
// Problem dims (fixed)
// ---------------------------------------------------------------------------
#define BATCH   32
#define SEQ     512
#define DMODEL  512
#define NHEADS  8
#define HDIM    64
#define DFF     2048
#define MTOK    (BATCH * SEQ)
#define LN_EPS  1e-12f

// ---------------------------------------------------------------------------
// Scratch (device globals)
// ---------------------------------------------------------------------------
__device__ float g_t0[MTOK * DMODEL];
__device__ float g_attnln[MTOK * DMODEL];

__device__ __nv_bfloat16 g_xhi[MTOK * DMODEL];
__device__ __nv_bfloat16 g_xlo[MTOK * DMODEL];
__device__ __nv_bfloat16 g_qhi[MTOK * DMODEL];
__device__ __nv_bfloat16 g_qlo[MTOK * DMODEL];
__device__ __nv_bfloat16 g_khi[MTOK * DMODEL];
__device__ __nv_bfloat16 g_klo[MTOK * DMODEL];
__device__ __nv_bfloat16 g_vhi[MTOK * DMODEL];
__device__ __nv_bfloat16 g_vlo[MTOK * DMODEL];
__device__ __nv_bfloat16 g_chi[MTOK * DMODEL];
__device__ __nv_bfloat16 g_clo[MTOK * DMODEL];
__device__ __nv_bfloat16 g_ahi[MTOK * DMODEL];
__device__ __nv_bfloat16 g_alo[MTOK * DMODEL];
__device__ __nv_bfloat16 g_fhi[MTOK * DFF];
__device__ __nv_bfloat16 g_flo[MTOK * DFF];

__device__ __nv_bfloat16 g_wqhi[DMODEL * DMODEL];
__device__ __nv_bfloat16 g_wqlo[DMODEL * DMODEL];
__device__ __nv_bfloat16 g_wkhi[DMODEL * DMODEL];
__device__ __nv_bfloat16 g_wklo[DMODEL * DMODEL];
__device__ __nv_bfloat16 g_wvhi[DMODEL * DMODEL];
__device__ __nv_bfloat16 g_wvlo[DMODEL * DMODEL];
__device__ __nv_bfloat16 g_wohi[DMODEL * DMODEL];
__device__ __nv_bfloat16 g_wolo[DMODEL * DMODEL];
__device__ __nv_bfloat16 g_w1hi[DFF * DMODEL];
__device__ __nv_bfloat16 g_w1lo[DFF * DMODEL];
__device__ __nv_bfloat16 g_w2hi[DMODEL * DFF];
__device__ __nv_bfloat16 g_w2lo[DMODEL * DFF];

// ---------------------------------------------------------------------------
// helpers
// ---------------------------------------------------------------------------
__device__ __forceinline__ void mma16816(float* c, const uint32_t* a, const uint32_t* b)
{
    asm volatile(
        "mma.sync.aligned.m16n8k16.row.col.f32.bf16.bf16.f32 "
        "{%0,%1,%2,%3}, {%4,%5,%6,%7}, {%8,%9}, {%0,%1,%2,%3};"
        : "+f"(c[0]), "+f"(c[1]), "+f"(c[2]), "+f"(c[3])
        : "r"(a[0]), "r"(a[1]), "r"(a[2]), "r"(a[3]), "r"(b[0]), "r"(b[1]));
}

__device__ __forceinline__ float fast_exp(float x) {
    float y = fmaxf(x * 1.4426950408889634f, -120.0f);
    float n = rintf(y);
    float f = y - n;
    float p = 1.3333558e-3f;
    p = fmaf(p, f, 9.6181291e-3f);
    p = fmaf(p, f, 5.5504109e-2f);
    p = fmaf(p, f, 2.4022651e-1f);
    p = fmaf(p, f, 6.9314718e-1f);
    p = fmaf(p, f, 1.0f);
    return p * __int_as_float(((int)n + 127) << 23);
}

__device__ __forceinline__ void split1(float v, unsigned short& h, unsigned short& l) {
    __nv_bfloat16 hb = __float2bfloat16_rn(v);
    float r = v - __bfloat162float(hb);
    __nv_bfloat16 lb = __float2bfloat16_rn(r);
    h = __bfloat16_as_ushort(hb);
    l = __bfloat16_as_ushort(lb);
}
__device__ __forceinline__ uint32_t pack2(unsigned short a, unsigned short b) {
    return (uint32_t)a | ((uint32_t)b << 16);
}

// ---------------------------------------------------------------------------
// fp32 -> bf16 hi/lo split (input x only)
// ---------------------------------------------------------------------------
__global__ void split_kernel(const float* __restrict__ X,
                             __nv_bfloat16* __restrict__ hi,
                             __nv_bfloat16* __restrict__ lo, int n4)
{
    int i = blockIdx.x * blockDim.x + threadIdx.x;
    if (i >= n4) return;
    float4 x = ((const float4*)X)[i];
    unsigned short h0, h1, h2, h3, l0, l1, l2, l3;
    split1(x.x, h0, l0); split1(x.y, h1, l1);
    split1(x.z, h2, l2); split1(x.w, h3, l3);
    uint2 hv, lv;
    hv.x = pack2(h0, h1); hv.y = pack2(h2, h3);
    lv.x = pack2(l0, l1); lv.y = pack2(l2, l3);
    ((uint2*)hi)[i] = hv;
    ((uint2*)lo)[i] = lv;
}

// Transpose + split: W[K][N] fp32 -> hi/lo [N][K] bf16
__global__ void tsplit_kernel(const float* __restrict__ W,
                              __nv_bfloat16* __restrict__ hi,
                              __nv_bfloat16* __restrict__ lo,
                              int K, int N)
{
    __shared__ float tile[32][33];
    const int n0 = blockIdx.x * 32, k0 = blockIdx.y * 32;
    const int tx = threadIdx.x, ty = threadIdx.y;
#pragma unroll
    for (int i = 0; i < 32; i += 8)
        tile[ty + i][tx] = W[(size_t)(k0 + ty + i) * N + n0 + tx];
    __syncthreads();
#pragma unroll
    for (int i = 0; i < 32; i += 8) {
        float v = tile[tx][ty + i];
        unsigned short h, l;
        split1(v, h, l);
        size_t o = (size_t)(n0 + ty + i) * K + k0 + tx;
        hi[o] = __ushort_as_bfloat16(h);
        lo[o] = __ushort_as_bfloat16(l);
    }
}

// ---------------------------------------------------------------------------
// Tensor-core split-GEMM (single-buffer mainloop — round-4 proven fast),
// multi-output epilogue: Cf fp32 (nullable) and/or Chi/Clo bf16 (nullable).
// CTA 128x64, k-tile 64, 8 warps.
// ---------------------------------------------------------------------------
#define SA 72
#define GM_A_ELEMS (128 * SA)
#define GM_B_ELEMS (64 * SA)
#define GM_SMEM_ELEMS (2 * GM_A_ELEMS + 2 * GM_B_ELEMS)
#define GM_SMEM_BYTES (GM_SMEM_ELEMS * 2)

__global__ __launch_bounds__(256)
void gemm_mma(const __nv_bfloat16* __restrict__ Ahi,
              const __nv_bfloat16* __restrict__ Alo,
              const __nv_bfloat16* __restrict__ Bhi,
              const __nv_bfloat16* __restrict__ Blo,
              const float* __restrict__ bias,
              float* __restrict__ Cf,
              __nv_bfloat16* __restrict__ Chi,
              __nv_bfloat16* __restrict__ Clo,
              int M, int N, int K, int do_gelu)
{
    extern __shared__ __nv_bfloat16 smb[];
    __nv_bfloat16* As_hi = smb;
    __nv_bfloat16* As_lo = smb + GM_A_ELEMS;
    __nv_bfloat16* Bs_hi = smb + 2 * GM_A_ELEMS;
    __nv_bfloat16* Bs_lo = smb + 2 * GM_A_ELEMS + GM_B_ELEMS;

    const int tid = threadIdx.x;
    const int wid = tid >> 5;
    const int lid = tid & 31;
    const int gID = lid >> 2;
    const int t4  = lid & 3;

    const int row0 = blockIdx.y * 128;
    const int col0 = blockIdx.x * 64;
    const int m_off = (wid & 3) * 32;
    const int n_off = (wid >> 2) * 32;

    float acc[2][4][4];
#pragma unroll
    for (int mi = 0; mi < 2; mi++)
#pragma unroll
        for (int ni = 0; ni < 4; ni++)
#pragma unroll
            for (int j = 0; j < 4; j++) acc[mi][ni][j] = 0.f;

    const int nT = K >> 6;
    for (int t = 0; t < nT; t++) {
        const int kb = t << 6;
#pragma unroll
        for (int i = 0; i < 4; i++) {
            int e = tid + i * 256;
            int r = e >> 3, g = e & 7;
            int ds = r * SA + g * 8;
            size_t src = (size_t)(row0 + r) * K + kb + g * 8;
            *(uint4*)&As_hi[ds] = *(const uint4*)&Ahi[src];
            *(uint4*)&As_lo[ds] = *(const uint4*)&Alo[src];
        }
#pragma unroll
        for (int i = 0; i < 2; i++) {
            int e = tid + i * 256;
            int r = e >> 3, g = e & 7;
            int ds = r * SA + g * 8;
            size_t src = (size_t)(col0 + r) * K + kb + g * 8;
            *(uint4*)&Bs_hi[ds] = *(const uint4*)&Bhi[src];
            *(uint4*)&Bs_lo[ds] = *(const uint4*)&Blo[src];
        }
        __syncthreads();

#pragma unroll
        for (int kk = 0; kk < 64; kk += 16) {
            uint32_t ahi[2][4], alo[2][4], bhi[4][2], blo[4][2];
#pragma unroll
            for (int mi = 0; mi < 2; mi++) {
                int r = m_off + mi * 16 + gID;
                int base0 = r * SA + kk + t4 * 2;
                int base1 = (r + 8) * SA + kk + t4 * 2;
                ahi[mi][0] = *(const uint32_t*)&As_hi[base0];
                ahi[mi][1] = *(const uint32_t*)&As_hi[base1];
                ahi[mi][2] = *(const uint32_t*)&As_hi[base0 + 8];
                ahi[mi][3] = *(const uint32_t*)&As_hi[base1 + 8];
                alo[mi][0] = *(const uint32_t*)&As_lo[base0];
                alo[mi][1] = *(const uint32_t*)&As_lo[base1];
                alo[mi][2] = *(const uint32_t*)&As_lo[base0 + 8];
                alo[mi][3] = *(const uint32_t*)&As_lo[base1 + 8];
            }
#pragma unroll
            for (int ni = 0; ni < 4; ni++) {
                int n = n_off + ni * 8 + gID;
                int base = n * SA + kk + t4 * 2;
                bhi[ni][0] = *(const uint32_t*)&Bs_hi[base];
                bhi[ni][1] = *(const uint32_t*)&Bs_hi[base + 8];
                blo[ni][0] = *(const uint32_t*)&Bs_lo[base];
                blo[ni][1] = *(const uint32_t*)&Bs_lo[base + 8];
            }
#pragma unroll
            for (int mi = 0; mi < 2; mi++)
#pragma unroll
                for (int ni = 0; ni < 4; ni++) {
                    mma16816(acc[mi][ni], ahi[mi], bhi[ni]);
                    mma16816(acc[mi][ni], alo[mi], bhi[ni]);
                    mma16816(acc[mi][ni], ahi[mi], blo[ni]);
                }
        }
        __syncthreads();
    }

    // ---- epilogue ----
#pragma unroll
    for (int mi = 0; mi < 2; mi++) {
#pragma unroll
        for (int ni = 0; ni < 4; ni++) {
            int col = col0 + n_off + ni * 8 + t4 * 2;
            float b0 = bias[col], b1 = bias[col + 1];
#pragma unroll
            for (int half = 0; half < 2; half++) {
                int row = row0 + m_off + mi * 16 + gID + half * 8;
                float v0 = acc[mi][ni][half * 2 + 0] + b0;
                float v1 = acc[mi][ni][half * 2 + 1] + b1;
                if (do_gelu) {
                    v0 = 0.5f * v0 * (1.0f + erff(v0 * 0.70710678118654752f));
                    v1 = 0.5f * v1 * (1.0f + erff(v1 * 0.70710678118654752f));
                }
                size_t o = (size_t)row * N + col;
                if (Cf) {
                    float2 fo; fo.x = v0; fo.y = v1;
                    *(float2*)(Cf + o) = fo;
                }
                if (Chi) {
                    unsigned short h0, h1, l0, l1;
                    split1(v0, h0, l0);
                    split1(v1, h1, l1);
                    *(uint32_t*)(Chi + o) = pack2(h0, h1);
                    *(uint32_t*)(Clo + o) = pack2(l0, l1);
                }
            }
        }
    }
}

// ---------------------------------------------------------------------------
// Tensor-core attention. Q/K/V arrive pre-split bf16. ctx written pre-split.
// ---------------------------------------------------------------------------
#define AT_SA   72
#define AT_QHI  0
#define AT_QLO  9216
#define AT_KHI  18432
#define AT_KLO  27648
#define AT_PHI  36864
#define AT_PLO  46080
#define AT_SS   55296
#define AT_INV  (AT_SS + 64 * 512 * 4)
#define AT_SMEM (AT_INV + 256)

__global__ __launch_bounds__(256)
void attn_mma(const __nv_bfloat16* __restrict__ Qhi_g,
              const __nv_bfloat16* __restrict__ Qlo_g,
              const __nv_bfloat16* __restrict__ Khi_g,
              const __nv_bfloat16* __restrict__ Klo_g,
              const __nv_bfloat16* __restrict__ Vhi_g,
              const __nv_bfloat16* __restrict__ Vlo_g,
              const float* __restrict__ mask,
              __nv_bfloat16* __restrict__ Chi_g,
              __nv_bfloat16* __restrict__ Clo_g)
{
    extern __shared__ char smc[];
    __nv_bfloat16* Qhi = (__nv_bfloat16*)(smc + AT_QHI);
    __nv_bfloat16* Qlo = (__nv_bfloat16*)(smc + AT_QLO);
    __nv_bfloat16* Khi = (__nv_bfloat16*)(smc + AT_KHI);
    __nv_bfloat16* Klo = (__nv_bfloat16*)(smc + AT_KLO);
    __nv_bfloat16* Phi = (__nv_bfloat16*)(smc + AT_PHI);
    __nv_bfloat16* Plo = (__nv_bfloat16*)(smc + AT_PLO);
    float* Ss   = (float*)(smc + AT_SS);
    float* invs = (float*)(smc + AT_INV);

    const int tid = threadIdx.x;
    const int wid = tid >> 5, lid = tid & 31;
    const int gID = lid >> 2, t4 = lid & 3;
    const int wm = wid & 3, wn = wid >> 2;
    const int q0 = blockIdx.x * 64;
    const int h = blockIdx.y, b = blockIdx.z;
    const size_t hb = ((size_t)b * SEQ) * DMODEL + (size_t)h * HDIM;
    const float* mbase = mask + (size_t)b * SEQ * SEQ;

    // load Q tile 64x64 (bf16 hi/lo, direct copy)
#pragma unroll
    for (int i = 0; i < 2; i++) {
        int e = tid + i * 256;
        int r = e >> 3, g = e & 7;
        size_t src = hb + (size_t)(q0 + r) * DMODEL + g * 8;
        int ds = r * AT_SA + g * 8;
        *(uint4*)(Qhi + ds) = *(const uint4*)(Qhi_g + src);
        *(uint4*)(Qlo + ds) = *(const uint4*)(Qlo_g + src);
    }

    float pv[4][4];
#pragma unroll
    for (int ni = 0; ni < 4; ni++)
#pragma unroll
        for (int j = 0; j < 4; j++) pv[ni][j] = 0.f;

    // ---- phase 1: scores ----
    for (int kc = 0; kc < 8; kc++) {
        const int k0 = kc * 64;
        __syncthreads();
#pragma unroll
        for (int i = 0; i < 2; i++) {
            int e = tid + i * 256;
            int r = e >> 3, g = e & 7;
            size_t src = hb + (size_t)(k0 + r) * DMODEL + g * 8;
            int ds = r * AT_SA + g * 8;
            *(uint4*)(Khi + ds) = *(const uint4*)(Khi_g + src);
            *(uint4*)(Klo + ds) = *(const uint4*)(Klo_g + src);
        }
        __syncthreads();

        float s[4][4];
#pragma unroll
        for (int ni = 0; ni < 4; ni++)
#pragma unroll
            for (int j = 0; j < 4; j++) s[ni][j] = 0.f;

#pragma unroll
        for (int kk = 0; kk < 64; kk += 16) {
            uint32_t ah[4], al[4];
            int rb0 = (wm * 16 + gID) * AT_SA + kk + t4 * 2;
            int rb1 = rb0 + 8 * AT_SA;
            ah[0] = *(const uint32_t*)&Qhi[rb0];
            ah[1] = *(const uint32_t*)&Qhi[rb1];
            ah[2] = *(const uint32_t*)&Qhi[rb0 + 8];
            ah[3] = *(const uint32_t*)&Qhi[rb1 + 8];
            al[0] = *(const uint32_t*)&Qlo[rb0];
            al[1] = *(const uint32_t*)&Qlo[rb1];
            al[2] = *(const uint32_t*)&Qlo[rb0 + 8];
            al[3] = *(const uint32_t*)&Qlo[rb1 + 8];
#pragma unroll
            for (int ni = 0; ni < 4; ni++) {
                int nb = (wn * 32 + ni * 8 + gID) * AT_SA + kk + t4 * 2;
                uint32_t bh[2], bl[2];
                bh[0] = *(const uint32_t*)&Khi[nb];
                bh[1] = *(const uint32_t*)&Khi[nb + 8];
                bl[0] = *(const uint32_t*)&Klo[nb];
                bl[1] = *(const uint32_t*)&Klo[nb + 8];
                mma16816(s[ni], ah, bh);
                mma16816(s[ni], al, bh);
                mma16816(s[ni], ah, bl);
            }
        }
#pragma unroll
        for (int ni = 0; ni < 4; ni++) {
            int col = k0 + wn * 32 + ni * 8 + t4 * 2;
#pragma unroll
            for (int hf = 0; hf < 2; hf++) {
                int row = wm * 16 + gID + hf * 8;
                float2 m2 = *(const float2*)(mbase + (size_t)(q0 + row) * SEQ + col);
                float2 o;
                o.x = s[ni][hf * 2 + 0] * 0.125f + m2.x;
                o.y = s[ni][hf * 2 + 1] * 0.125f + m2.y;
                *(float2*)(Ss + row * 512 + col) = o;
            }
        }
    }
    __syncthreads();

    // ---- phase 2: softmax ----
    {
#pragma unroll
        for (int rr = 0; rr < 8; rr++) {
            int r = wid * 8 + rr;
            float* row = Ss + r * 512;
            float4 v[4];
#pragma unroll
            for (int it = 0; it < 4; it++)
                v[it] = *(float4*)(row + it * 128 + lid * 4);
            float m = -1e30f;
#pragma unroll
            for (int it = 0; it < 4; it++)
                m = fmaxf(m, fmaxf(fmaxf(v[it].x, v[it].y), fmaxf(v[it].z, v[it].w)));
#pragma unroll
            for (int off = 16; off; off >>= 1)
                m = fmaxf(m, __shfl_xor_sync(0xffffffffu, m, off));
            float sum = 0.f;
#pragma unroll
            for (int it = 0; it < 4; it++) {
                v[it].x = fast_exp(v[it].x - m);
                v[it].y = fast_exp(v[it].y - m);
                v[it].z = fast_exp(v[it].z - m);
                v[it].w = fast_exp(v[it].w - m);
                sum += v[it].x + v[it].y + v[it].z + v[it].w;
                *(float4*)(row + it * 128 + lid * 4) = v[it];
            }
#pragma unroll
            for (int off = 16; off; off >>= 1)
                sum += __shfl_xor_sync(0xffffffffu, sum, off);
            if (lid == 0) invs[r] = 1.0f / sum;
        }
    }

    // ---- phase 3: P @ V ----
    for (int kc = 0; kc < 8; kc++) {
        const int k0 = kc * 64;
        __syncthreads();

        // P chunk: normalize + split
        {
            int r = tid >> 2, c0 = (tid & 3) * 16;
            float is = invs[r];
#pragma unroll
            for (int j2 = 0; j2 < 2; j2++) {
                const float* src = Ss + r * 512 + k0 + c0 + j2 * 8;
                float4 a = *(const float4*)(src);
                float4 bq = *(const float4*)(src + 4);
                float vals[8] = {a.x * is, a.y * is, a.z * is, a.w * is,
                                 bq.x * is, bq.y * is, bq.z * is, bq.w * is};
                unsigned short hh[8], ll[8];
#pragma unroll
                for (int j = 0; j < 8; j++) split1(vals[j], hh[j], ll[j]);
                uint4 hv, lv;
                hv.x = pack2(hh[0], hh[1]); hv.y = pack2(hh[2], hh[3]);
                hv.z = pack2(hh[4], hh[5]); hv.w = pack2(hh[6], hh[7]);
                lv.x = pack2(ll[0], ll[1]); lv.y = pack2(ll[2], ll[3]);
                lv.z = pack2(ll[4], ll[5]); lv.w = pack2(ll[6], ll[7]);
                *(uint4*)(Phi + r * AT_SA + c0 + j2 * 8) = hv;
                *(uint4*)(Plo + r * AT_SA + c0 + j2 * 8) = lv;
            }
        }

        // V chunk: transpose (bf16)
#pragma unroll
        for (int i = 0; i < 4; i++) {
            int e = tid + i * 256;
            int r = e >> 4, c4 = e & 15;
            size_t src = hb + (size_t)(k0 + r) * DMODEL + c4 * 4;
            uint2 hv = *(const uint2*)(Vhi_g + src);
            uint2 lv = *(const uint2*)(Vlo_g + src);
            __nv_bfloat16 h0 = __ushort_as_bfloat16((unsigned short)(hv.x & 0xffff));
            __nv_bfloat16 h1 = __ushort_as_bfloat16((unsigned short)(hv.x >> 16));
            __nv_bfloat16 h2 = __ushort_as_bfloat16((unsigned short)(hv.y & 0xffff));
            __nv_bfloat16 h3 = __ushort_as_bfloat16((unsigned short)(hv.y >> 16));
            __nv_bfloat16 l0 = __ushort_as_bfloat16((unsigned short)(lv.x & 0xffff));
            __nv_bfloat16 l1 = __ushort_as_bfloat16((unsigned short)(lv.x >> 16));
            __nv_bfloat16 l2 = __ushort_as_bfloat16((unsigned short)(lv.y & 0xffff));
            __nv_bfloat16 l3 = __ushort_as_bfloat16((unsigned short)(lv.y >> 16));
            int d = c4 * 4;
            Khi[(d + 0) * AT_SA + r] = h0;  Klo[(d + 0) * AT_SA + r] = l0;
            Khi[(d + 1) * AT_SA + r] = h1;  Klo[(d + 1) * AT_SA + r] = l1;
            Khi[(d + 2) * AT_SA + r] = h2;  Klo[(d + 2) * AT_SA + r] = l2;
            Khi[(d + 3) * AT_SA + r] = h3;  Klo[(d + 3) * AT_SA + r] = l3;
        }
        __syncthreads();

#pragma unroll
        for (int kk = 0; kk < 64; kk += 16) {
            uint32_t ah[4], al[4];
            int rb0 = (wm * 16 + gID) * AT_SA + kk + t4 * 2;
            int rb1 = rb0 + 8 * AT_SA;
            ah[0] = *(const uint32_t*)&Phi[rb0];
            ah[1] = *(const uint32_t*)&Phi[rb1];
            ah[2] = *(const uint32_t*)&Phi[rb0 + 8];
            ah[3] = *(const uint32_t*)&Phi[rb1 + 8];
            al[0] = *(const uint32_t*)&Plo[rb0];
            al[1] = *(const uint32_t*)&Plo[rb1];
            al[2] = *(const uint32_t*)&Plo[rb0 + 8];
            al[3] = *(const uint32_t*)&Plo[rb1 + 8];
#pragma unroll
            for (int ni = 0; ni < 4; ni++) {
                int nb = (wn * 32 + ni * 8 + gID) * AT_SA + kk + t4 * 2;
                uint32_t bh[2], bl[2];
                bh[0] = *(const uint32_t*)&Khi[nb];
                bh[1] = *(const uint32_t*)&Khi[nb + 8];
                bl[0] = *(const uint32_t*)&Klo[nb];
                bl[1] = *(const uint32_t*)&Klo[nb + 8];
                mma16816(pv[ni], ah, bh);
                mma16816(pv[ni], al, bh);
                mma16816(pv[ni], ah, bl);
            }
        }
    }

    // ---- write ctx as bf16 hi/lo ----
#pragma unroll
    for (int ni = 0; ni < 4; ni++) {
        int d = wn * 32 + ni * 8 + t4 * 2;
#pragma unroll
        for (int hf = 0; hf < 2; hf++) {
            int row = wm * 16 + gID + hf * 8;
            unsigned short h0, h1, l0, l1;
            split1(pv[ni][hf * 2 + 0], h0, l0);
            split1(pv[ni][hf * 2 + 1], h1, l1);
            size_t o = hb + (size_t)(q0 + row) * DMODEL + d;
            *(uint32_t*)(Chi_g + o) = pack2(h0, h1);
            *(uint32_t*)(Clo_g + o) = pack2(l0, l1);
        }
    }
}

// ---------------------------------------------------------------------------
// LayerNorm + residual; optional bf16 hi/lo side outputs
// ---------------------------------------------------------------------------
__global__ void ln_residual_kernel(const float* __restrict__ y,
                                   const float* __restrict__ res,
                                   const float* __restrict__ g,
                                   const float* __restrict__ bta,
                                   float* __restrict__ out,
                                   __nv_bfloat16* __restrict__ ohi,
                                   __nv_bfloat16* __restrict__ olo)
{
    __shared__ float red[256];
    const int r = blockIdx.x;
    const int tid = threadIdx.x;
    const size_t off = (size_t)r * DMODEL;

    float v0 = y[off + tid]        + res[off + tid];
    float v1 = y[off + tid + 256]  + res[off + tid + 256];

    red[tid] = v0 + v1;
    __syncthreads();
#pragma unroll
    for (int s = 128; s; s >>= 1) {
        if (tid < s) red[tid] += red[tid + s];
        __syncthreads();
    }
    float mean = red[0] * (1.0f / 512.0f);
    __syncthreads();

    float d0 = v0 - mean, d1 = v1 - mean;
    red[tid] = d0 * d0 + d1 * d1;
    __syncthreads();
#pragma unroll
    for (int s = 128; s; s >>= 1) {
        if (tid < s) red[tid] += red[tid + s];
        __syncthreads();
    }
    float inv = rsqrtf(red[0] * (1.0f / 512.0f) + LN_EPS);

    float o0 = d0 * inv * g[tid]       + bta[tid];
    float o1 = d1 * inv * g[tid + 256] + bta[tid + 256];
    out[off + tid]       = o0;
    out[off + tid + 256] = o1;
    if (ohi) {
        unsigned short h, l;
        split1(o0, h, l);
        ohi[off + tid] = __ushort_as_bfloat16(h);
        olo[off + tid] = __ushort_as_bfloat16(l);
        split1(o1, h, l);
        ohi[off + tid + 256] = __ushort_as_bfloat16(h);
        olo[off + tid + 256] = __ushort_as_bfloat16(l);
    }
}

// ---------------------------------------------------------------------------
// launch
// ---------------------------------------------------------------------------
extern "C" void kernel_launch(void* const* d_in, const int* in_sizes, int n_in,
                              void* d_out, int out_size)
{
    const float* x     = (const float*)d_in[0];
    const float* mask  = (const float*)d_in[1];
    const float* Wq    = (const float*)d_in[2];
    const float* bq    = (const float*)d_in[3];
    const float* Wk    = (const float*)d_in[4];
    const float* bk    = (const float*)d_in[5];
    const float* Wv    = (const float*)d_in[6];
    const float* bv    = (const float*)d_in[7];
    const float* Wo    = (const float*)d_in[8];
    const float* bo    = (const float*)d_in[9];
    const float* ln1g  = (const float*)d_in[10];
    const float* ln1b  = (const float*)d_in[11];
    const float* W1    = (const float*)d_in[12];
    const float* b1    = (const float*)d_in[13];
    const float* W2    = (const float*)d_in[14];
    const float* b2    = (const float*)d_in[15];
    const float* ln2g  = (const float*)d_in[16];
    const float* ln2b  = (const float*)d_in[17];
    float* out = (float*)d_out;

    float *t0, *aln;
    cudaGetSymbolAddress((void**)&t0,  g_t0);
    cudaGetSymbolAddress((void**)&aln, g_attnln);

    __nv_bfloat16 *xhi, *xlo, *qhi, *qlo, *khi, *klo, *vhi, *vlo;
    __nv_bfloat16 *chi, *clo, *ahi, *alo, *fhi, *flo;
    cudaGetSymbolAddress((void**)&xhi, g_xhi);
    cudaGetSymbolAddress((void**)&xlo, g_xlo);
    cudaGetSymbolAddress((void**)&qhi, g_qhi);
    cudaGetSymbolAddress((void**)&qlo, g_qlo);
    cudaGetSymbolAddress((void**)&khi, g_khi);
    cudaGetSymbolAddress((void**)&klo, g_klo);
    cudaGetSymbolAddress((void**)&vhi, g_vhi);
    cudaGetSymbolAddress((void**)&vlo, g_vlo);
    cudaGetSymbolAddress((void**)&chi, g_chi);
    cudaGetSymbolAddress((void**)&clo, g_clo);
    cudaGetSymbolAddress((void**)&ahi, g_ahi);
    cudaGetSymbolAddress((void**)&alo, g_alo);
    cudaGetSymbolAddress((void**)&fhi, g_fhi);
    cudaGetSymbolAddress((void**)&flo, g_flo);

    __nv_bfloat16 *wqh, *wql, *wkh, *wkl, *wvh, *wvl, *woh, *wol, *w1h, *w1l, *w2h, *w2l;
    cudaGetSymbolAddress((void**)&wqh, g_wqhi);
    cudaGetSymbolAddress((void**)&wql, g_wqlo);
    cudaGetSymbolAddress((void**)&wkh, g_wkhi);
    cudaGetSymbolAddress((void**)&wkl, g_wklo);
    cudaGetSymbolAddress((void**)&wvh, g_wvhi);
    cudaGetSymbolAddress((void**)&wvl, g_wvlo);
    cudaGetSymbolAddress((void**)&woh, g_wohi);
    cudaGetSymbolAddress((void**)&wol, g_wolo);
    cudaGetSymbolAddress((void**)&w1h, g_w1hi);
    cudaGetSymbolAddress((void**)&w1l, g_w1lo);
    cudaGetSymbolAddress((void**)&w2h, g_w2hi);
    cudaGetSymbolAddress((void**)&w2l, g_w2lo);

    cudaFuncSetAttribute(attn_mma,
                         cudaFuncAttributeMaxDynamicSharedMemorySize, AT_SMEM);
    cudaFuncSetAttribute(gemm_mma,
                         cudaFuncAttributeMaxDynamicSharedMemorySize, GM_SMEM_BYTES);

    dim3 tb(32, 8);

    // weight transpose + split
    tsplit_kernel<<<dim3(DMODEL / 32, DMODEL / 32), tb>>>(Wq, wqh, wql, DMODEL, DMODEL);
    tsplit_kernel<<<dim3(DMODEL / 32, DMODEL / 32), tb>>>(Wk, wkh, wkl, DMODEL, DMODEL);
    tsplit_kernel<<<dim3(DMODEL / 32, DMODEL / 32), tb>>>(Wv, wvh, wvl, DMODEL, DMODEL);
    tsplit_kernel<<<dim3(DMODEL / 32, DMODEL / 32), tb>>>(Wo, woh, wol, DMODEL, DMODEL);
    tsplit_kernel<<<dim3(DFF / 32, DMODEL / 32), tb>>>(W1, w1h, w1l, DMODEL, DFF);
    tsplit_kernel<<<dim3(DMODEL / 32, DFF / 32), tb>>>(W2, w2h, w2l, DFF, DMODEL);

    // split input x
    {
        int n4 = MTOK * DMODEL / 4;
        split_kernel<<<(n4 + 255) / 256, 256>>>(x, xhi, xlo, n4);
    }

    // QKV projections -> bf16 hi/lo directly
    {
        dim3 grid(DMODEL / 64, MTOK / 128);
        gemm_mma<<<grid, 256, GM_SMEM_BYTES>>>(xhi, xlo, wqh, wql, bq,
                                               nullptr, qhi, qlo,
                                               MTOK, DMODEL, DMODEL, 0);
        gemm_mma<<<grid, 256, GM_SMEM_BYTES>>>(xhi, xlo, wkh, wkl, bk,
                                               nullptr, khi, klo,
                                               MTOK, DMODEL, DMODEL, 0);
        gemm_mma<<<grid, 256, GM_SMEM_BYTES>>>(xhi, xlo, wvh, wvl, bv,
                                               nullptr, vhi, vlo,
                                               MTOK, DMODEL, DMODEL, 0);
    }

    // attention -> ctx bf16 hi/lo directly
    {
        dim3 grid(SEQ / 64, NHEADS, BATCH);
        attn_mma<<<grid, 256, AT_SMEM>>>(qhi, qlo, khi, klo, vhi, vlo,
                                         mask, chi, clo);
    }

    // output projection + residual LN (LN emits fp32 + bf16 hi/lo)
    {
        dim3 grid(DMODEL / 64, MTOK / 128);
        gemm_mma<<<grid, 256, GM_SMEM_BYTES>>>(chi, clo, woh, wol, bo,
                                               t0, nullptr, nullptr,
                                               MTOK, DMODEL, DMODEL, 0);
        ln_residual_kernel<<<MTOK, 256>>>(t0, x, ln1g, ln1b, aln, ahi, alo);
    }

    // FFN
    {
        dim3 grid1(DFF / 64, MTOK / 128);
        gemm_mma<<<grid1, 256, GM_SMEM_BYTES>>>(ahi, alo, w1h, w1l, b1,
                                                nullptr, fhi, flo,
                                                MTOK, DFF, DMODEL, 1);
        dim3 grid2(DMODEL / 64, MTOK / 128);
        gemm_mma<<<grid2, 256, GM_SMEM_BYTES>>>(fhi, flo, w2h, w2l, b2,
                                                t0, nullptr, nullptr,
                                                MTOK, DMODEL, DFF, 0);
        ln_residual_kernel<<<MTOK, 256>>>(t0, aln, ln2g, ln2b, out,
                                          nullptr, nullptr);
    }
}

// round 7
// speedup vs baseline: 1.1485x; 1.0314x over previous
#include <cuda_runtime.h>
#include <cuda_bf16.h>
#include <math.h>
#include <stdint.h>

// ---------------------------------------------------------------------------
// Problem dims (fixed)
// ---------------------------------------------------------------------------
#define BATCH   32
#define SEQ     512
#define DMODEL  512
#define NHEADS  8
#define HDIM    64
#define DFF     2048
#define MTOK    (BATCH * SEQ)
#define LN_EPS  1e-12f

// ---------------------------------------------------------------------------
// Scratch (device globals)
// ---------------------------------------------------------------------------
__device__ float g_t0[MTOK * DMODEL];
__device__ float g_attnln[MTOK * DMODEL];

__device__ __nv_bfloat16 g_xhi[MTOK * DMODEL];
__device__ __nv_bfloat16 g_xlo[MTOK * DMODEL];
__device__ __nv_bfloat16 g_qhi[MTOK * DMODEL];
__device__ __nv_bfloat16 g_qlo[MTOK * DMODEL];
__device__ __nv_bfloat16 g_khi[MTOK * DMODEL];
__device__ __nv_bfloat16 g_klo[MTOK * DMODEL];
__device__ __nv_bfloat16 g_vhi[MTOK * DMODEL];
__device__ __nv_bfloat16 g_vlo[MTOK * DMODEL];
__device__ __nv_bfloat16 g_chi[MTOK * DMODEL];
__device__ __nv_bfloat16 g_clo[MTOK * DMODEL];
__device__ __nv_bfloat16 g_ahi[MTOK * DMODEL];
__device__ __nv_bfloat16 g_alo[MTOK * DMODEL];
__device__ __nv_bfloat16 g_fhi[MTOK * DFF];
__device__ __nv_bfloat16 g_flo[MTOK * DFF];

__device__ __nv_bfloat16 g_wqhi[DMODEL * DMODEL];
__device__ __nv_bfloat16 g_wqlo[DMODEL * DMODEL];
__device__ __nv_bfloat16 g_wkhi[DMODEL * DMODEL];
__device__ __nv_bfloat16 g_wklo[DMODEL * DMODEL];
__device__ __nv_bfloat16 g_wvhi[DMODEL * DMODEL];
__device__ __nv_bfloat16 g_wvlo[DMODEL * DMODEL];
__device__ __nv_bfloat16 g_wohi[DMODEL * DMODEL];
__device__ __nv_bfloat16 g_wolo[DMODEL * DMODEL];
__device__ __nv_bfloat16 g_w1hi[DFF * DMODEL];
__device__ __nv_bfloat16 g_w1lo[DFF * DMODEL];
__device__ __nv_bfloat16 g_w2hi[DMODEL * DFF];
__device__ __nv_bfloat16 g_w2lo[DMODEL * DFF];

// ---------------------------------------------------------------------------
// helpers
// ---------------------------------------------------------------------------
__device__ __forceinline__ void mma16816(float* c, const uint32_t* a, const uint32_t* b)
{
    asm volatile(
        "mma.sync.aligned.m16n8k16.row.col.f32.bf16.bf16.f32 "
        "{%0,%1,%2,%3}, {%4,%5,%6,%7}, {%8,%9}, {%0,%1,%2,%3};"
        : "+f"(c[0]), "+f"(c[1]), "+f"(c[2]), "+f"(c[3])
        : "r"(a[0]), "r"(a[1]), "r"(a[2]), "r"(a[3]), "r"(b[0]), "r"(b[1]));
}

__device__ __forceinline__ uint32_t smem_u32(const void* p) {
    uint32_t a;
    asm("{ .reg .u64 t; cvta.to.shared.u64 t, %1; cvt.u32.u64 %0, t; }"
        : "=r"(a) : "l"(p));
    return a;
}

__device__ __forceinline__ void cp16(uint32_t dst, const void* src) {
    asm volatile("cp.async.cg.shared.global [%0], [%1], 16;"
                 :: "r"(dst), "l"(src));
}
__device__ __forceinline__ void cp_commit() {
    asm volatile("cp.async.commit_group;" ::: "memory");
}
template <int N>
__device__ __forceinline__ void cp_wait() {
    asm volatile("cp.async.wait_group %0;" :: "n"(N) : "memory");
}

__device__ __forceinline__ float fast_exp(float x) {
    float y = fmaxf(x * 1.4426950408889634f, -120.0f);
    float n = rintf(y);
    float f = y - n;
    float p = 1.3333558e-3f;
    p = fmaf(p, f, 9.6181291e-3f);
    p = fmaf(p, f, 5.5504109e-2f);
    p = fmaf(p, f, 2.4022651e-1f);
    p = fmaf(p, f, 6.9314718e-1f);
    p = fmaf(p, f, 1.0f);
    return p * __int_as_float(((int)n + 127) << 23);
}

__device__ __forceinline__ void split1(float v, unsigned short& h, unsigned short& l) {
    __nv_bfloat16 hb = __float2bfloat16_rn(v);
    float r = v - __bfloat162float(hb);
    __nv_bfloat16 lb = __float2bfloat16_rn(r);
    h = __bfloat16_as_ushort(hb);
    l = __bfloat16_as_ushort(lb);
}
__device__ __forceinline__ uint32_t pack2(unsigned short a, unsigned short b) {
    return (uint32_t)a | ((uint32_t)b << 16);
}

// ---------------------------------------------------------------------------
// fp32 -> bf16 hi/lo split (input x only)
// ---------------------------------------------------------------------------
__global__ void split_kernel(const float* __restrict__ X,
                             __nv_bfloat16* __restrict__ hi,
                             __nv_bfloat16* __restrict__ lo, int n4)
{
    int i = blockIdx.x * blockDim.x + threadIdx.x;
    if (i >= n4) return;
    float4 x = ((const float4*)X)[i];
    unsigned short h0, h1, h2, h3, l0, l1, l2, l3;
    split1(x.x, h0, l0); split1(x.y, h1, l1);
    split1(x.z, h2, l2); split1(x.w, h3, l3);
    uint2 hv, lv;
    hv.x = pack2(h0, h1); hv.y = pack2(h2, h3);
    lv.x = pack2(l0, l1); lv.y = pack2(l2, l3);
    ((uint2*)hi)[i] = hv;
    ((uint2*)lo)[i] = lv;
}

// Transpose + split: W[K][N] fp32 -> hi/lo [N][K] bf16
__global__ void tsplit_kernel(const float* __restrict__ W,
                              __nv_bfloat16* __restrict__ hi,
                              __nv_bfloat16* __restrict__ lo,
                              int K, int N)
{
    __shared__ float tile[32][33];
    const int n0 = blockIdx.x * 32, k0 = blockIdx.y * 32;
    const int tx = threadIdx.x, ty = threadIdx.y;
#pragma unroll
    for (int i = 0; i < 32; i += 8)
        tile[ty + i][tx] = W[(size_t)(k0 + ty + i) * N + n0 + tx];
    __syncthreads();
#pragma unroll
    for (int i = 0; i < 32; i += 8) {
        float v = tile[tx][ty + i];
        unsigned short h, l;
        split1(v, h, l);
        size_t o = (size_t)(n0 + ty + i) * K + k0 + tx;
        hi[o] = __ushort_as_bfloat16(h);
        lo[o] = __ushort_as_bfloat16(l);
    }
}

// ---------------------------------------------------------------------------
// Pipelined tensor-core split-GEMM: k-tile 32, 2-stage cp.async,
// stage = 30 KB -> 60 KB smem total -> 3 CTAs/SM preserved.
// CTA 128x64, 8 warps. Multi-output epilogue.
// ---------------------------------------------------------------------------
#define SA2 40
#define ST2_A (128 * SA2)                 // 5120 elems
#define ST2_B (64 * SA2)                  // 2560 elems
#define STAGE2 (2 * ST2_A + 2 * ST2_B)    // 15360 elems
#define GM_SMEM_BYTES (2 * STAGE2 * 2)    // 61440 bytes

__global__ __launch_bounds__(256)
void gemm_mma(const __nv_bfloat16* __restrict__ Ahi,
              const __nv_bfloat16* __restrict__ Alo,
              const __nv_bfloat16* __restrict__ Bhi,
              const __nv_bfloat16* __restrict__ Blo,
              const float* __restrict__ bias,
              float* __restrict__ Cf,
              __nv_bfloat16* __restrict__ Chi,
              __nv_bfloat16* __restrict__ Clo,
              int M, int N, int K, int do_gelu)
{
    extern __shared__ __nv_bfloat16 smb[];
    const uint32_t sm_base = smem_u32(smb);

    const int tid = threadIdx.x;
    const int wid = tid >> 5;
    const int lid = tid & 31;
    const int gID = lid >> 2;
    const int t4  = lid & 3;

    const int row0 = blockIdx.y * 128;
    const int col0 = blockIdx.x * 64;
    const int m_off = (wid & 3) * 32;
    const int n_off = (wid >> 2) * 32;

    // loader coords: A 128 rows x 4 chunks (8 bf16 ea), 512 chunks, 2/thread
    //                B 64 rows x 4 chunks, 256 chunks, 1/thread
    auto load_stage = [&](int buf, int t) {
        const int kb = t << 5;
        uint32_t base = sm_base + (uint32_t)buf * (STAGE2 * 2);
#pragma unroll
        for (int i = 0; i < 2; i++) {
            int e = tid + i * 256;
            int r = e >> 2, g = e & 3;
            uint32_t ds = (uint32_t)(r * SA2 + g * 8) * 2;
            size_t src = (size_t)(row0 + r) * K + kb + g * 8;
            cp16(base + ds, Ahi + src);
            cp16(base + ST2_A * 2 + ds, Alo + src);
        }
        {
            int r = tid >> 2, g = tid & 3;
            uint32_t ds = (uint32_t)(r * SA2 + g * 8) * 2;
            size_t src = (size_t)(col0 + r) * K + kb + g * 8;
            cp16(base + 2 * ST2_A * 2 + ds, Bhi + src);
            cp16(base + 2 * ST2_A * 2 + ST2_B * 2 + ds, Blo + src);
        }
        cp_commit();
    };

    float acc[2][4][4];
#pragma unroll
    for (int mi = 0; mi < 2; mi++)
#pragma unroll
        for (int ni = 0; ni < 4; ni++)
#pragma unroll
            for (int j = 0; j < 4; j++) acc[mi][ni][j] = 0.f;

    const int nT = K >> 5;
    load_stage(0, 0);

    for (int t = 0; t < nT; t++) {
        const int buf = t & 1;
        if (t + 1 < nT) {
            load_stage(1 - buf, t + 1);
            cp_wait<1>();
        } else {
            cp_wait<0>();
        }
        __syncthreads();

        const __nv_bfloat16* As_hi = smb + buf * STAGE2;
        const __nv_bfloat16* As_lo = As_hi + ST2_A;
        const __nv_bfloat16* Bs_hi = As_hi + 2 * ST2_A;
        const __nv_bfloat16* Bs_lo = Bs_hi + ST2_B;

#pragma unroll
        for (int kk = 0; kk < 32; kk += 16) {
            uint32_t ahi[2][4], alo[2][4], bhi[4][2], blo[4][2];
#pragma unroll
            for (int mi = 0; mi < 2; mi++) {
                int r = m_off + mi * 16 + gID;
                int base0 = r * SA2 + kk + t4 * 2;
                int base1 = (r + 8) * SA2 + kk + t4 * 2;
                ahi[mi][0] = *(const uint32_t*)&As_hi[base0];
                ahi[mi][1] = *(const uint32_t*)&As_hi[base1];
                ahi[mi][2] = *(const uint32_t*)&As_hi[base0 + 8];
                ahi[mi][3] = *(const uint32_t*)&As_hi[base1 + 8];
                alo[mi][0] = *(const uint32_t*)&As_lo[base0];
                alo[mi][1] = *(const uint32_t*)&As_lo[base1];
                alo[mi][2] = *(const uint32_t*)&As_lo[base0 + 8];
                alo[mi][3] = *(const uint32_t*)&As_lo[base1 + 8];
            }
#pragma unroll
            for (int ni = 0; ni < 4; ni++) {
                int n = n_off + ni * 8 + gID;
                int base = n * SA2 + kk + t4 * 2;
                bhi[ni][0] = *(const uint32_t*)&Bs_hi[base];
                bhi[ni][1] = *(const uint32_t*)&Bs_hi[base + 8];
                blo[ni][0] = *(const uint32_t*)&Bs_lo[base];
                blo[ni][1] = *(const uint32_t*)&Bs_lo[base + 8];
            }
#pragma unroll
            for (int mi = 0; mi < 2; mi++)
#pragma unroll
                for (int ni = 0; ni < 4; ni++) {
                    mma16816(acc[mi][ni], ahi[mi], bhi[ni]);
                    mma16816(acc[mi][ni], alo[mi], bhi[ni]);
                    mma16816(acc[mi][ni], ahi[mi], blo[ni]);
                }
        }
        __syncthreads();
    }

    // ---- epilogue ----
#pragma unroll
    for (int mi = 0; mi < 2; mi++) {
#pragma unroll
        for (int ni = 0; ni < 4; ni++) {
            int col = col0 + n_off + ni * 8 + t4 * 2;
            float b0 = bias[col], b1 = bias[col + 1];
#pragma unroll
            for (int half = 0; half < 2; half++) {
                int row = row0 + m_off + mi * 16 + gID + half * 8;
                float v0 = acc[mi][ni][half * 2 + 0] + b0;
                float v1 = acc[mi][ni][half * 2 + 1] + b1;
                if (do_gelu) {
                    v0 = 0.5f * v0 * (1.0f + erff(v0 * 0.70710678118654752f));
                    v1 = 0.5f * v1 * (1.0f + erff(v1 * 0.70710678118654752f));
                }
                size_t o = (size_t)row * N + col;
                if (Cf) {
                    float2 fo; fo.x = v0; fo.y = v1;
                    *(float2*)(Cf + o) = fo;
                }
                if (Chi) {
                    unsigned short h0, h1, l0, l1;
                    split1(v0, h0, l0);
                    split1(v1, h1, l1);
                    *(uint32_t*)(Chi + o) = pack2(h0, h1);
                    *(uint32_t*)(Clo + o) = pack2(l0, l1);
                }
            }
        }
    }
}

// ---------------------------------------------------------------------------
// Tensor-core attention. Q/K/V pre-split bf16; ctx written pre-split.
// Phase-1 K chunks double-buffered via cp.async.
// ---------------------------------------------------------------------------
#define AT_SA   72
#define AT_QHI  0
#define AT_QLO  9216
#define AT_K0   18432                 // KHI buf0 (KLO at +9216)
#define AT_K1   36864                 // KHI buf1
#define AT_PHI  55296
#define AT_PLO  64512
#define AT_SS   73728
#define AT_INV  (AT_SS + 64 * 512 * 4)    // 204800
#define AT_SMEM (AT_INV + 256)            // 205056

__global__ __launch_bounds__(256)
void attn_mma(const __nv_bfloat16* __restrict__ Qhi_g,
              const __nv_bfloat16* __restrict__ Qlo_g,
              const __nv_bfloat16* __restrict__ Khi_g,
              const __nv_bfloat16* __restrict__ Klo_g,
              const __nv_bfloat16* __restrict__ Vhi_g,
              const __nv_bfloat16* __restrict__ Vlo_g,
              const float* __restrict__ mask,
              __nv_bfloat16* __restrict__ Chi_g,
              __nv_bfloat16* __restrict__ Clo_g)
{
    extern __shared__ char smc[];
    const uint32_t sm_base = smem_u32(smc);
    __nv_bfloat16* Qhi = (__nv_bfloat16*)(smc + AT_QHI);
    __nv_bfloat16* Qlo = (__nv_bfloat16*)(smc + AT_QLO);
    __nv_bfloat16* Phi = (__nv_bfloat16*)(smc + AT_PHI);
    __nv_bfloat16* Plo = (__nv_bfloat16*)(smc + AT_PLO);
    float* Ss   = (float*)(smc + AT_SS);
    float* invs = (float*)(smc + AT_INV);

    const int tid = threadIdx.x;
    const int wid = tid >> 5, lid = tid & 31;
    const int gID = lid >> 2, t4 = lid & 3;
    const int wm = wid & 3, wn = wid >> 2;
    const int q0 = blockIdx.x * 64;
    const int h = blockIdx.y, b = blockIdx.z;
    const size_t hb = ((size_t)b * SEQ) * DMODEL + (size_t)h * HDIM;
    const float* mbase = mask + (size_t)b * SEQ * SEQ;

    // async K-chunk loader (64x64 hi/lo)
    auto load_k = [&](int bb, int kc) {
        const int k0 = kc * 64;
        uint32_t kh = sm_base + AT_K0 + (uint32_t)bb * 18432;
        uint32_t kl = kh + 9216;
#pragma unroll
        for (int i = 0; i < 2; i++) {
            int e = tid + i * 256;
            int r = e >> 3, g = e & 7;
            size_t src = hb + (size_t)(k0 + r) * DMODEL + g * 8;
            uint32_t ds = (uint32_t)(r * AT_SA + g * 8) * 2;
            cp16(kh + ds, Khi_g + src);
            cp16(kl + ds, Klo_g + src);
        }
        cp_commit();
    };

    load_k(0, 0);

    // load Q tile 64x64 (direct copy)
#pragma unroll
    for (int i = 0; i < 2; i++) {
        int e = tid + i * 256;
        int r = e >> 3, g = e & 7;
        size_t src = hb + (size_t)(q0 + r) * DMODEL + g * 8;
        int ds = r * AT_SA + g * 8;
        *(uint4*)(Qhi + ds) = *(const uint4*)(Qhi_g + src);
        *(uint4*)(Qlo + ds) = *(const uint4*)(Qlo_g + src);
    }

    float pv[4][4];
#pragma unroll
    for (int ni = 0; ni < 4; ni++)
#pragma unroll
        for (int j = 0; j < 4; j++) pv[ni][j] = 0.f;

    // ---- phase 1: scores (pipelined K) ----
    for (int kc = 0; kc < 8; kc++) {
        const int k0 = kc * 64;
        if (kc + 1 < 8) {
            load_k((kc + 1) & 1, kc + 1);
            cp_wait<1>();
        } else {
            cp_wait<0>();
        }
        __syncthreads();

        const __nv_bfloat16* Khi = (const __nv_bfloat16*)(smc + AT_K0 + (kc & 1) * 18432);
        const __nv_bfloat16* Klo = Khi + 4608;   // 9216 bytes = 4608 elems

        float s[4][4];
#pragma unroll
        for (int ni = 0; ni < 4; ni++)
#pragma unroll
            for (int j = 0; j < 4; j++) s[ni][j] = 0.f;

#pragma unroll
        for (int kk = 0; kk < 64; kk += 16) {
            uint32_t ah[4], al[4];
            int rb0 = (wm * 16 + gID) * AT_SA + kk + t4 * 2;
            int rb1 = rb0 + 8 * AT_SA;
            ah[0] = *(const uint32_t*)&Qhi[rb0];
            ah[1] = *(const uint32_t*)&Qhi[rb1];
            ah[2] = *(const uint32_t*)&Qhi[rb0 + 8];
            ah[3] = *(const uint32_t*)&Qhi[rb1 + 8];
            al[0] = *(const uint32_t*)&Qlo[rb0];
            al[1] = *(const uint32_t*)&Qlo[rb1];
            al[2] = *(const uint32_t*)&Qlo[rb0 + 8];
            al[3] = *(const uint32_t*)&Qlo[rb1 + 8];
#pragma unroll
            for (int ni = 0; ni < 4; ni++) {
                int nb = (wn * 32 + ni * 8 + gID) * AT_SA + kk + t4 * 2;
                uint32_t bh[2], bl[2];
                bh[0] = *(const uint32_t*)&Khi[nb];
                bh[1] = *(const uint32_t*)&Khi[nb + 8];
                bl[0] = *(const uint32_t*)&Klo[nb];
                bl[1] = *(const uint32_t*)&Klo[nb + 8];
                mma16816(s[ni], ah, bh);
                mma16816(s[ni], al, bh);
                mma16816(s[ni], ah, bl);
            }
        }
#pragma unroll
        for (int ni = 0; ni < 4; ni++) {
            int col = k0 + wn * 32 + ni * 8 + t4 * 2;
#pragma unroll
            for (int hf = 0; hf < 2; hf++) {
                int row = wm * 16 + gID + hf * 8;
                float2 m2 = *(const float2*)(mbase + (size_t)(q0 + row) * SEQ + col);
                float2 o;
                o.x = s[ni][hf * 2 + 0] * 0.125f + m2.x;
                o.y = s[ni][hf * 2 + 1] * 0.125f + m2.y;
                *(float2*)(Ss + row * 512 + col) = o;
            }
        }
        __syncthreads();
    }

    // ---- phase 2: softmax ----
    {
#pragma unroll
        for (int rr = 0; rr < 8; rr++) {
            int r = wid * 8 + rr;
            float* row = Ss + r * 512;
            float4 v[4];
#pragma unroll
            for (int it = 0; it < 4; it++)
                v[it] = *(float4*)(row + it * 128 + lid * 4);
            float m = -1e30f;
#pragma unroll
            for (int it = 0; it < 4; it++)
                m = fmaxf(m, fmaxf(fmaxf(v[it].x, v[it].y), fmaxf(v[it].z, v[it].w)));
#pragma unroll
            for (int off = 16; off; off >>= 1)
                m = fmaxf(m, __shfl_xor_sync(0xffffffffu, m, off));
            float sum = 0.f;
#pragma unroll
            for (int it = 0; it < 4; it++) {
                v[it].x = fast_exp(v[it].x - m);
                v[it].y = fast_exp(v[it].y - m);
                v[it].z = fast_exp(v[it].z - m);
                v[it].w = fast_exp(v[it].w - m);
                sum += v[it].x + v[it].y + v[it].z + v[it].w;
                *(float4*)(row + it * 128 + lid * 4) = v[it];
            }
#pragma unroll
            for (int off = 16; off; off >>= 1)
                sum += __shfl_xor_sync(0xffffffffu, sum, off);
            if (lid == 0) invs[r] = 1.0f / sum;
        }
    }

    // ---- phase 3: P @ V (V transposed into K buf0) ----
    __nv_bfloat16* Vth = (__nv_bfloat16*)(smc + AT_K0);
    __nv_bfloat16* Vtl = Vth + 4608;
    for (int kc = 0; kc < 8; kc++) {
        const int k0 = kc * 64;
        __syncthreads();

        // P chunk: normalize + split
        {
            int r = tid >> 2, c0 = (tid & 3) * 16;
            float is = invs[r];
#pragma unroll
            for (int j2 = 0; j2 < 2; j2++) {
                const float* src = Ss + r * 512 + k0 + c0 + j2 * 8;
                float4 a = *(const float4*)(src);
                float4 bq = *(const float4*)(src + 4);
                float vals[8] = {a.x * is, a.y * is, a.z * is, a.w * is,
                                 bq.x * is, bq.y * is, bq.z * is, bq.w * is};
                unsigned short hh[8], ll[8];
#pragma unroll
                for (int j = 0; j < 8; j++) split1(vals[j], hh[j], ll[j]);
                uint4 hv, lv;
                hv.x = pack2(hh[0], hh[1]); hv.y = pack2(hh[2], hh[3]);
                hv.z = pack2(hh[4], hh[5]); hv.w = pack2(hh[6], hh[7]);
                lv.x = pack2(ll[0], ll[1]); lv.y = pack2(ll[2], ll[3]);
                lv.z = pack2(ll[4], ll[5]); lv.w = pack2(ll[6], ll[7]);
                *(uint4*)(Phi + r * AT_SA + c0 + j2 * 8) = hv;
                *(uint4*)(Plo + r * AT_SA + c0 + j2 * 8) = lv;
            }
        }

        // V chunk: transpose (bf16)
#pragma unroll
        for (int i = 0; i < 4; i++) {
            int e = tid + i * 256;
            int r = e >> 4, c4 = e & 15;
            size_t src = hb + (size_t)(k0 + r) * DMODEL + c4 * 4;
            uint2 hv = *(const uint2*)(Vhi_g + src);
            uint2 lv = *(const uint2*)(Vlo_g + src);
            int d = c4 * 4;
            Vth[(d + 0) * AT_SA + r] = __ushort_as_bfloat16((unsigned short)(hv.x & 0xffff));
            Vth[(d + 1) * AT_SA + r] = __ushort_as_bfloat16((unsigned short)(hv.x >> 16));
            Vth[(d + 2) * AT_SA + r] = __ushort_as_bfloat16((unsigned short)(hv.y & 0xffff));
            Vth[(d + 3) * AT_SA + r] = __ushort_as_bfloat16((unsigned short)(hv.y >> 16));
            Vtl[(d + 0) * AT_SA + r] = __ushort_as_bfloat16((unsigned short)(lv.x & 0xffff));
            Vtl[(d + 1) * AT_SA + r] = __ushort_as_bfloat16((unsigned short)(lv.x >> 16));
            Vtl[(d + 2) * AT_SA + r] = __ushort_as_bfloat16((unsigned short)(lv.y & 0xffff));
            Vtl[(d + 3) * AT_SA + r] = __ushort_as_bfloat16((unsigned short)(lv.y >> 16));
        }
        __syncthreads();

#pragma unroll
        for (int kk = 0; kk < 64; kk += 16) {
            uint32_t ah[4], al[4];
            int rb0 = (wm * 16 + gID) * AT_SA + kk + t4 * 2;
            int rb1 = rb0 + 8 * AT_SA;
            ah[0] = *(const uint32_t*)&Phi[rb0];
            ah[1] = *(const uint32_t*)&Phi[rb1];
            ah[2] = *(const uint32_t*)&Phi[rb0 + 8];
            ah[3] = *(const uint32_t*)&Phi[rb1 + 8];
            al[0] = *(const uint32_t*)&Plo[rb0];
            al[1] = *(const uint32_t*)&Plo[rb1];
            al[2] = *(const uint32_t*)&Plo[rb0 + 8];
            al[3] = *(const uint32_t*)&Plo[rb1 + 8];
#pragma unroll
            for (int ni = 0; ni < 4; ni++) {
                int nb = (wn * 32 + ni * 8 + gID) * AT_SA + kk + t4 * 2;
                uint32_t bh[2], bl[2];
                bh[0] = *(const uint32_t*)&Vth[nb];
                bh[1] = *(const uint32_t*)&Vth[nb + 8];
                bl[0] = *(const uint32_t*)&Vtl[nb];
                bl[1] = *(const uint32_t*)&Vtl[nb + 8];
                mma16816(pv[ni], ah, bh);
                mma16816(pv[ni], al, bh);
                mma16816(pv[ni], ah, bl);
            }
        }
    }

    // ---- write ctx as bf16 hi/lo ----
#pragma unroll
    for (int ni = 0; ni < 4; ni++) {
        int d = wn * 32 + ni * 8 + t4 * 2;
#pragma unroll
        for (int hf = 0; hf < 2; hf++) {
            int row = wm * 16 + gID + hf * 8;
            unsigned short h0, h1, l0, l1;
            split1(pv[ni][hf * 2 + 0], h0, l0);
            split1(pv[ni][hf * 2 + 1], h1, l1);
            size_t o = hb + (size_t)(q0 + row) * DMODEL + d;
            *(uint32_t*)(Chi_g + o) = pack2(h0, h1);
            *(uint32_t*)(Clo_g + o) = pack2(l0, l1);
        }
    }
}

// ---------------------------------------------------------------------------
// LayerNorm + residual; optional bf16 hi/lo side outputs
// ---------------------------------------------------------------------------
__global__ void ln_residual_kernel(const float* __restrict__ y,
                                   const float* __restrict__ res,
                                   const float* __restrict__ g,
                                   const float* __restrict__ bta,
                                   float* __restrict__ out,
                                   __nv_bfloat16* __restrict__ ohi,
                                   __nv_bfloat16* __restrict__ olo)
{
    __shared__ float red[256];
    const int r = blockIdx.x;
    const int tid = threadIdx.x;
    const size_t off = (size_t)r * DMODEL;

    float v0 = y[off + tid]        + res[off + tid];
    float v1 = y[off + tid + 256]  + res[off + tid + 256];

    red[tid] = v0 + v1;
    __syncthreads();
#pragma unroll
    for (int s = 128; s; s >>= 1) {
        if (tid < s) red[tid] += red[tid + s];
        __syncthreads();
    }
    float mean = red[0] * (1.0f / 512.0f);
    __syncthreads();

    float d0 = v0 - mean, d1 = v1 - mean;
    red[tid] = d0 * d0 + d1 * d1;
    __syncthreads();
#pragma unroll
    for (int s = 128; s; s >>= 1) {
        if (tid < s) red[tid] += red[tid + s];
        __syncthreads();
    }
    float inv = rsqrtf(red[0] * (1.0f / 512.0f) + LN_EPS);

    float o0 = d0 * inv * g[tid]       + bta[tid];
    float o1 = d1 * inv * g[tid + 256] + bta[tid + 256];
    out[off + tid]       = o0;
    out[off + tid + 256] = o1;
    if (ohi) {
        unsigned short h, l;
        split1(o0, h, l);
        ohi[off + tid] = __ushort_as_bfloat16(h);
        olo[off + tid] = __ushort_as_bfloat16(l);
        split1(o1, h, l);
        ohi[off + tid + 256] = __ushort_as_bfloat16(h);
        olo[off + tid + 256] = __ushort_as_bfloat16(l);
    }
}

// ---------------------------------------------------------------------------
// launch
// ---------------------------------------------------------------------------
extern "C" void kernel_launch(void* const* d_in, const int* in_sizes, int n_in,
                              void* d_out, int out_size)
{
    const float* x     = (const float*)d_in[0];
    const float* mask  = (const float*)d_in[1];
    const float* Wq    = (const float*)d_in[2];
    const float* bq    = (const float*)d_in[3];
    const float* Wk    = (const float*)d_in[4];
    const float* bk    = (const float*)d_in[5];
    const float* Wv    = (const float*)d_in[6];
    const float* bv    = (const float*)d_in[7];
    const float* Wo    = (const float*)d_in[8];
    const float* bo    = (const float*)d_in[9];
    const float* ln1g  = (const float*)d_in[10];
    const float* ln1b  = (const float*)d_in[11];
    const float* W1    = (const float*)d_in[12];
    const float* b1    = (const float*)d_in[13];
    const float* W2    = (const float*)d_in[14];
    const float* b2    = (const float*)d_in[15];
    const float* ln2g  = (const float*)d_in[16];
    const float* ln2b  = (const float*)d_in[17];
    float* out = (float*)d_out;

    float *t0, *aln;
    cudaGetSymbolAddress((void**)&t0,  g_t0);
    cudaGetSymbolAddress((void**)&aln, g_attnln);

    __nv_bfloat16 *xhi, *xlo, *qhi, *qlo, *khi, *klo, *vhi, *vlo;
    __nv_bfloat16 *chi, *clo, *ahi, *alo, *fhi, *flo;
    cudaGetSymbolAddress((void**)&xhi, g_xhi);
    cudaGetSymbolAddress((void**)&xlo, g_xlo);
    cudaGetSymbolAddress((void**)&qhi, g_qhi);
    cudaGetSymbolAddress((void**)&qlo, g_qlo);
    cudaGetSymbolAddress((void**)&khi, g_khi);
    cudaGetSymbolAddress((void**)&klo, g_klo);
    cudaGetSymbolAddress((void**)&vhi, g_vhi);
    cudaGetSymbolAddress((void**)&vlo, g_vlo);
    cudaGetSymbolAddress((void**)&chi, g_chi);
    cudaGetSymbolAddress((void**)&clo, g_clo);
    cudaGetSymbolAddress((void**)&ahi, g_ahi);
    cudaGetSymbolAddress((void**)&alo, g_alo);
    cudaGetSymbolAddress((void**)&fhi, g_fhi);
    cudaGetSymbolAddress((void**)&flo, g_flo);

    __nv_bfloat16 *wqh, *wql, *wkh, *wkl, *wvh, *wvl, *woh, *wol, *w1h, *w1l, *w2h, *w2l;
    cudaGetSymbolAddress((void**)&wqh, g_wqhi);
    cudaGetSymbolAddress((void**)&wql, g_wqlo);
    cudaGetSymbolAddress((void**)&wkh, g_wkhi);
    cudaGetSymbolAddress((void**)&wkl, g_wklo);
    cudaGetSymbolAddress((void**)&wvh, g_wvhi);
    cudaGetSymbolAddress((void**)&wvl, g_wvlo);
    cudaGetSymbolAddress((void**)&woh, g_wohi);
    cudaGetSymbolAddress((void**)&wol, g_wolo);
    cudaGetSymbolAddress((void**)&w1h, g_w1hi);
    cudaGetSymbolAddress((void**)&w1l, g_w1lo);
    cudaGetSymbolAddress((void**)&w2h, g_w2hi);
    cudaGetSymbolAddress((void**)&w2l, g_w2lo);

    cudaFuncSetAttribute(attn_mma,
                         cudaFuncAttributeMaxDynamicSharedMemorySize, AT_SMEM);
    cudaFuncSetAttribute(gemm_mma,
                         cudaFuncAttributeMaxDynamicSharedMemorySize, GM_SMEM_BYTES);

    dim3 tb(32, 8);

    // weight transpose + split
    tsplit_kernel<<<dim3(DMODEL / 32, DMODEL / 32), tb>>>(Wq, wqh, wql, DMODEL, DMODEL);
    tsplit_kernel<<<dim3(DMODEL / 32, DMODEL / 32), tb>>>(Wk, wkh, wkl, DMODEL, DMODEL);
    tsplit_kernel<<<dim3(DMODEL / 32, DMODEL / 32), tb>>>(Wv, wvh, wvl, DMODEL, DMODEL);
    tsplit_kernel<<<dim3(DMODEL / 32, DMODEL / 32), tb>>>(Wo, woh, wol, DMODEL, DMODEL);
    tsplit_kernel<<<dim3(DFF / 32, DMODEL / 32), tb>>>(W1, w1h, w1l, DMODEL, DFF);
    tsplit_kernel<<<dim3(DMODEL / 32, DFF / 32), tb>>>(W2, w2h, w2l, DFF, DMODEL);

    // split input x
    {
        int n4 = MTOK * DMODEL / 4;
        split_kernel<<<(n4 + 255) / 256, 256>>>(x, xhi, xlo, n4);
    }

    // QKV projections -> bf16 hi/lo directly
    {
        dim3 grid(DMODEL / 64, MTOK / 128);
        gemm_mma<<<grid, 256, GM_SMEM_BYTES>>>(xhi, xlo, wqh, wql, bq,
                                               nullptr, qhi, qlo,
                                               MTOK, DMODEL, DMODEL, 0);
        gemm_mma<<<grid, 256, GM_SMEM_BYTES>>>(xhi, xlo, wkh, wkl, bk,
                                               nullptr, khi, klo,
                                               MTOK, DMODEL, DMODEL, 0);
        gemm_mma<<<grid, 256, GM_SMEM_BYTES>>>(xhi, xlo, wvh, wvl, bv,
                                               nullptr, vhi, vlo,
                                               MTOK, DMODEL, DMODEL, 0);
    }

    // attention -> ctx bf16 hi/lo directly
    {
        dim3 grid(SEQ / 64, NHEADS, BATCH);
        attn_mma<<<grid, 256, AT_SMEM>>>(qhi, qlo, khi, klo, vhi, vlo,
                                         mask, chi, clo);
    }

    // output projection + residual LN (LN emits fp32 + bf16 hi/lo)
    {
        dim3 grid(DMODEL / 64, MTOK / 128);
        gemm_mma<<<grid, 256, GM_SMEM_BYTES>>>(chi, clo, woh, wol, bo,
                                               t0, nullptr, nullptr,
                                               MTOK, DMODEL, DMODEL, 0);
        ln_residual_kernel<<<MTOK, 256>>>(t0, x, ln1g, ln1b, aln, ahi, alo);
    }

    // FFN
    {
        dim3 grid1(DFF / 64, MTOK / 128);
        gemm_mma<<<grid1, 256, GM_SMEM_BYTES>>>(ahi, alo, w1h, w1l, b1,
                                                nullptr, fhi, flo,
                                                MTOK, DFF, DMODEL, 1);
        dim3 grid2(DMODEL / 64, MTOK / 128);
        gemm_mma<<<grid2, 256, GM_SMEM_BYTES>>>(fhi, flo, w2h, w2l, b2,
                                                t0, nullptr, nullptr,
                                                MTOK, DMODEL, DFF, 0);
        ln_residual_kernel<<<MTOK, 256>>>(t0, aln, ln2g, ln2b, out,
                                          nullptr, nullptr);
    }
}